// round 1
// baseline (speedup 1.0000x reference)
#include <cuda_runtime.h>

// Problem constants (fixed by the reference)
#define BT  128                 // threads per block = rows per block
#define HH  64                  // hidden size
#define GG  192                 // 3*H gates
#define TT  12                  // timesteps (enc and dec)
#define CC  10                  // clusters
#define NN  325                 // nodes
#define BB  32                  // batch
#define BNR (BB*NN)             // 10400 flattened rows

typedef unsigned long long u64;

// Scratch for decoder outputs, layout [row][t][c] so the mix kernel reads 10
// contiguous floats per output element. 10400*12*10*4B ~= 5 MB.
__device__ float g_vals[BNR * TT * CC];

// ---- packed f32x2 helpers (Blackwell packed fp32 pipe: 2 FMAs/instr) ----
__device__ __forceinline__ u64 pk(float lo, float hi) {
    u64 r; asm("mov.b64 %0, {%1,%2};" : "=l"(r) : "f"(lo), "f"(hi)); return r;
}
__device__ __forceinline__ float2 unpk(u64 v) {
    float2 r; asm("mov.b64 {%0,%1}, %2;" : "=f"(r.x), "=f"(r.y) : "l"(v)); return r;
}
__device__ __forceinline__ void fma2(u64 &d, u64 a, u64 b) {
    asm("fma.rn.f32x2 %0, %1, %2, %0;" : "+l"(d) : "l"(a), "l"(b));
}

__device__ __forceinline__ float sigm(float x) {
    return __fdividef(1.0f, 1.0f + __expf(-x));
}
__device__ __forceinline__ float tanh_(float x) {
    // tanh(x) = 2*sigmoid(2x) - 1 ; saturates correctly for large |x|
    return __fmaf_rn(2.0f, sigm(2.0f * x), -1.0f);
}

// One GRU step for one (cluster,row) per thread.
//   sW  : Whh [192][64] row-major in SMEM (broadcast reads)
//   sGC : per-gate constants [192][4] = {wih0, wih1, bih, bhh}
//   sH  : current h staged column-wise [64][BT]; updated in place (each
//         thread touches only its own column -> no intra-loop syncs needed)
//   h2  : current h packed in registers (32 x f32x2), refreshed at the end
__device__ __forceinline__ void gru_step(const float* __restrict__ sW,
                                         const float* __restrict__ sGC,
                                         float* __restrict__ sH,
                                         int tid, u64 (&h2)[32],
                                         float x0, float x1)
{
    #pragma unroll 1
    for (int j = 0; j < HH; j++) {
        const float4* wr = (const float4*)(sW + j * HH);
        const float4* wz = (const float4*)(sW + (j + HH) * HH);
        const float4* wn = (const float4*)(sW + (j + 2 * HH) * HH);
        u64 ar = pk(0.f, 0.f), az = pk(0.f, 0.f), an = pk(0.f, 0.f);
        #pragma unroll
        for (int kk = 0; kk < 16; kk++) {
            float4 a = wr[kk]; float4 b = wz[kk]; float4 d = wn[kk];
            fma2(ar, pk(a.x, a.y), h2[2*kk]); fma2(ar, pk(a.z, a.w), h2[2*kk+1]);
            fma2(az, pk(b.x, b.y), h2[2*kk]); fma2(az, pk(b.z, b.w), h2[2*kk+1]);
            fma2(an, pk(d.x, d.y), h2[2*kk]); fma2(an, pk(d.z, d.w), h2[2*kk+1]);
        }
        float4 cr = ((const float4*)sGC)[j];
        float4 cz = ((const float4*)sGC)[j + HH];
        float4 cn = ((const float4*)sGC)[j + 2 * HH];
        float2 arf = unpk(ar), azf = unpk(az), anf = unpk(an);
        float ghr = arf.x + arf.y + cr.w;
        float ghz = azf.x + azf.y + cz.w;
        float ghn = anf.x + anf.y + cn.w;
        float gir = cr.x * x0 + cr.y * x1 + cr.z;
        float giz = cz.x * x0 + cz.y * x1 + cz.z;
        float gin = cn.x * x0 + cn.y * x1 + cn.z;
        float rg = sigm(gir + ghr);
        float zg = sigm(giz + ghz);
        float ng = tanh_(gin + rg * ghn);
        float hold = sH[j * BT + tid];
        sH[j * BT + tid] = (1.0f - zg) * ng + zg * hold;
    }
    // refresh packed register copy of h from SMEM (own column only)
    #pragma unroll
    for (int kk = 0; kk < 32; kk++)
        h2[kk] = pk(sH[(2*kk) * BT + tid], sH[(2*kk+1) * BT + tid]);
}

extern "C" __global__ void __launch_bounds__(BT, 2)
rnn_kernel(const float* __restrict__ X,
           const float* __restrict__ eWih, const float* __restrict__ eWhh,
           const float* __restrict__ ebih, const float* __restrict__ ebhh,
           const float* __restrict__ dWih, const float* __restrict__ dWhh,
           const float* __restrict__ dbih, const float* __restrict__ dbhh,
           const float* __restrict__ linW, const float* __restrict__ linb)
{
    extern __shared__ float sm[];
    float* sW   = sm;              // 12288 floats (48 KB): Whh of current phase
    float* sGC  = sm + 12288;      // 768 floats: per-gate {wih0,wih1,bih,bhh}
    float* sLin = sm + 13056;      // 68 floats: lin_W (64) + lin_b
    float* sH   = sm + 13124;      // 8192 floats: h staged [64][BT]

    const int tid = threadIdx.x;
    const int c   = blockIdx.y;
    const int r   = blockIdx.x * BT + tid;
    const bool valid = (r < BNR);
    const int rr = valid ? r : (BNR - 1);

    // ---- stage encoder weights ----
    {
        const float4* g4 = (const float4*)(eWhh + (size_t)c * GG * HH);
        float4* s4 = (float4*)sW;
        for (int i = tid; i < GG * HH / 4; i += BT) s4[i] = g4[i];
        for (int g = tid; g < GG; g += BT) {
            sGC[g*4+0] = eWih[c*GG*2 + g*2];
            sGC[g*4+1] = eWih[c*GG*2 + g*2 + 1];
            sGC[g*4+2] = ebih[c*GG + g];
            sGC[g*4+3] = ebhh[c*GG + g];
        }
        for (int i = tid; i < HH * BT; i += BT) sH[i] = 0.0f;
    }
    __syncthreads();

    u64 h2[32];
    #pragma unroll
    for (int i = 0; i < 32; i++) h2[i] = pk(0.f, 0.f);

    // ---- encoder: 12 steps, x prefetched one step ahead ----
    const float* xr = X + (size_t)rr * (TT * 2);
    float2 xt = *(const float2*)xr;
    for (int t = 0; t < TT; t++) {
        float2 xn = (t < TT - 1) ? *(const float2*)(xr + (t + 1) * 2) : xt;
        gru_step(sW, sGC, sH, tid, h2, xt.x, xt.y);
        xt = xn;
    }
    float lv = xt.x;   // last observed feature-0 value

    // ---- restage with decoder weights ----
    __syncthreads();
    {
        const float4* g4 = (const float4*)(dWhh + (size_t)c * GG * HH);
        float4* s4 = (float4*)sW;
        for (int i = tid; i < GG * HH / 4; i += BT) s4[i] = g4[i];
        for (int g = tid; g < GG; g += BT) {
            sGC[g*4+0] = dWih[c*GG + g];
            sGC[g*4+1] = 0.0f;
            sGC[g*4+2] = dbih[c*GG + g];
            sGC[g*4+3] = dbhh[c*GG + g];
        }
        for (int k = tid; k < HH; k += BT) sLin[k] = linW[c*HH + k];
        if (tid == 0) sLin[64] = linb[c];
    }
    __syncthreads();
    const float lb = sLin[64];

    // ---- decoder: 12 steps, lin projection feeds back as input ----
    for (int t = 0; t < TT; t++) {
        gru_step(sW, sGC, sH, tid, h2, lv, 0.0f);
        u64 acc = pk(0.f, 0.f);
        const float4* lw = (const float4*)sLin;
        #pragma unroll
        for (int kk = 0; kk < 16; kk++) {
            float4 w = lw[kk];
            fma2(acc, pk(w.x, w.y), h2[2*kk]);
            fma2(acc, pk(w.z, w.w), h2[2*kk+1]);
        }
        float2 af = unpk(acc);
        float value = af.x + af.y + lb;
        if (valid) g_vals[(r * TT + t) * CC + c] = value;
        lv = value;
    }
}

// out[b,n,t] = sum_c vals[b,n,t,c] * softmax(embed[n])[c]
extern "C" __global__ void mix_kernel(const float* __restrict__ embed,
                                      float* __restrict__ out)
{
    int i = blockIdx.x * blockDim.x + threadIdx.x;   // i = r*12 + t
    if (i >= BNR * TT) return;
    int n = (i / TT) % NN;
    const float* e = embed + n * CC;
    float m = e[0];
    #pragma unroll
    for (int cc = 1; cc < CC; cc++) m = fmaxf(m, e[cc]);
    const float* v = g_vals + i * CC;
    float s = 0.0f, acc = 0.0f;
    #pragma unroll
    for (int cc = 0; cc < CC; cc++) {
        float w = __expf(e[cc] - m);
        s += w;
        acc += v[cc] * w;
    }
    out[i] = __fdividef(acc, s);
}

extern "C" void kernel_launch(void* const* d_in, const int* in_sizes, int n_in,
                              void* d_out, int out_size)
{
    // metadata order: A, X, enc_Wih, enc_Whh, enc_bih, enc_bhh,
    //                 dec_Wih, dec_Whh, dec_bih, dec_bhh, lin_W, lin_b, embed
    const float* X     = (const float*)d_in[1];
    const float* eWih  = (const float*)d_in[2];
    const float* eWhh  = (const float*)d_in[3];
    const float* ebih  = (const float*)d_in[4];
    const float* ebhh  = (const float*)d_in[5];
    const float* dWih  = (const float*)d_in[6];
    const float* dWhh  = (const float*)d_in[7];
    const float* dbih  = (const float*)d_in[8];
    const float* dbhh  = (const float*)d_in[9];
    const float* linW  = (const float*)d_in[10];
    const float* linb  = (const float*)d_in[11];
    const float* embed = (const float*)d_in[12];
    float* out = (float*)d_out;

    const int smem_bytes = (13124 + HH * BT) * (int)sizeof(float);  // 85264 B
    cudaFuncSetAttribute((const void*)rnn_kernel,
                         cudaFuncAttributeMaxDynamicSharedMemorySize, smem_bytes);

    dim3 grid((BNR + BT - 1) / BT, CC);   // (82, 10)
    rnn_kernel<<<grid, BT, smem_bytes>>>(X, eWih, eWhh, ebih, ebhh,
                                         dWih, dWhh, dbih, dbhh, linW, linb);
    mix_kernel<<<(BNR * TT + 255) / 256, 256>>>(embed, out);
}

// round 2
// speedup vs baseline: 1.0004x; 1.0004x over previous
#include <cuda_runtime.h>

// Problem constants (fixed by the reference)
#define BT  128                 // threads per block = rows per block
#define HH  64                  // hidden size
#define GG  192                 // 3*H gates
#define TT  12                  // timesteps (enc and dec)
#define CC  10                  // clusters
#define NN  325                 // nodes
#define BB  32                  // batch
#define BNR (BB*NN)             // 10400 flattened rows

typedef unsigned long long u64;

// Scratch for decoder outputs, layout [row][t][c] so the mix kernel reads 10
// contiguous floats per output element. 10400*12*10*4B ~= 5 MB.
__device__ float g_vals[BNR * TT * CC];

// ---- packed f32x2 helpers (Blackwell packed fp32 pipe: 2 FMAs/instr) ----
__device__ __forceinline__ u64 pk(float lo, float hi) {
    u64 r; asm("mov.b64 %0, {%1,%2};" : "=l"(r) : "f"(lo), "f"(hi)); return r;
}
__device__ __forceinline__ float2 unpk(u64 v) {
    float2 r; asm("mov.b64 {%0,%1}, %2;" : "=f"(r.x), "=f"(r.y) : "l"(v)); return r;
}
__device__ __forceinline__ void fma2(u64 &d, u64 a, u64 b) {
    asm("fma.rn.f32x2 %0, %1, %2, %0;" : "+l"(d) : "l"(a), "l"(b));
}

__device__ __forceinline__ float sigm(float x) {
    return __fdividef(1.0f, 1.0f + __expf(-x));
}
__device__ __forceinline__ float tanh_(float x) {
    // tanh(x) = 2*sigmoid(2x) - 1 ; saturates correctly for large |x|
    return __fmaf_rn(2.0f, sigm(2.0f * x), -1.0f);
}

// One GRU step for one (cluster,row) per thread.
//   sW  : Whh [192][64] row-major in SMEM (broadcast reads)
//   sGC : per-gate constants [192][4] = {wih0, wih1, bih, bhh}
//   sH  : current h staged column-wise [64][BT]; updated in place (each
//         thread touches only its own column -> no intra-loop syncs needed)
//   h2  : current h packed in registers (32 x f32x2), refreshed at the end
__device__ __forceinline__ void gru_step(const float* __restrict__ sW,
                                         const float* __restrict__ sGC,
                                         float* __restrict__ sH,
                                         int tid, u64 (&h2)[32],
                                         float x0, float x1)
{
    #pragma unroll 1
    for (int j = 0; j < HH; j++) {
        const float4* wr = (const float4*)(sW + j * HH);
        const float4* wz = (const float4*)(sW + (j + HH) * HH);
        const float4* wn = (const float4*)(sW + (j + 2 * HH) * HH);
        u64 ar = pk(0.f, 0.f), az = pk(0.f, 0.f), an = pk(0.f, 0.f);
        #pragma unroll
        for (int kk = 0; kk < 16; kk++) {
            float4 a = wr[kk]; float4 b = wz[kk]; float4 d = wn[kk];
            fma2(ar, pk(a.x, a.y), h2[2*kk]); fma2(ar, pk(a.z, a.w), h2[2*kk+1]);
            fma2(az, pk(b.x, b.y), h2[2*kk]); fma2(az, pk(b.z, b.w), h2[2*kk+1]);
            fma2(an, pk(d.x, d.y), h2[2*kk]); fma2(an, pk(d.z, d.w), h2[2*kk+1]);
        }
        float4 cr = ((const float4*)sGC)[j];
        float4 cz = ((const float4*)sGC)[j + HH];
        float4 cn = ((const float4*)sGC)[j + 2 * HH];
        float2 arf = unpk(ar), azf = unpk(az), anf = unpk(an);
        float ghr = arf.x + arf.y + cr.w;
        float ghz = azf.x + azf.y + cz.w;
        float ghn = anf.x + anf.y + cn.w;
        float gir = cr.x * x0 + cr.y * x1 + cr.z;
        float giz = cz.x * x0 + cz.y * x1 + cz.z;
        float gin = cn.x * x0 + cn.y * x1 + cn.z;
        float rg = sigm(gir + ghr);
        float zg = sigm(giz + ghz);
        float ng = tanh_(gin + rg * ghn);
        float hold = sH[j * BT + tid];
        sH[j * BT + tid] = (1.0f - zg) * ng + zg * hold;
    }
    // refresh packed register copy of h from SMEM (own column only)
    #pragma unroll
    for (int kk = 0; kk < 32; kk++)
        h2[kk] = pk(sH[(2*kk) * BT + tid], sH[(2*kk+1) * BT + tid]);
}

extern "C" __global__ void __launch_bounds__(BT, 2)
rnn_kernel(const float* __restrict__ X,
           const float* __restrict__ eWih, const float* __restrict__ eWhh,
           const float* __restrict__ ebih, const float* __restrict__ ebhh,
           const float* __restrict__ dWih, const float* __restrict__ dWhh,
           const float* __restrict__ dbih, const float* __restrict__ dbhh,
           const float* __restrict__ linW, const float* __restrict__ linb)
{
    extern __shared__ float sm[];
    float* sW   = sm;              // 12288 floats (48 KB): Whh of current phase
    float* sGC  = sm + 12288;      // 768 floats: per-gate {wih0,wih1,bih,bhh}
    float* sLin = sm + 13056;      // 68 floats: lin_W (64) + lin_b
    float* sH   = sm + 13124;      // 8192 floats: h staged [64][BT]

    const int tid = threadIdx.x;
    const int c   = blockIdx.y;
    const int r   = blockIdx.x * BT + tid;
    const bool valid = (r < BNR);
    const int rr = valid ? r : (BNR - 1);

    // ---- stage encoder weights ----
    {
        const float4* g4 = (const float4*)(eWhh + (size_t)c * GG * HH);
        float4* s4 = (float4*)sW;
        for (int i = tid; i < GG * HH / 4; i += BT) s4[i] = g4[i];
        for (int g = tid; g < GG; g += BT) {
            sGC[g*4+0] = eWih[c*GG*2 + g*2];
            sGC[g*4+1] = eWih[c*GG*2 + g*2 + 1];
            sGC[g*4+2] = ebih[c*GG + g];
            sGC[g*4+3] = ebhh[c*GG + g];
        }
        for (int i = tid; i < HH * BT; i += BT) sH[i] = 0.0f;
    }
    __syncthreads();

    u64 h2[32];
    #pragma unroll
    for (int i = 0; i < 32; i++) h2[i] = pk(0.f, 0.f);

    // ---- encoder: 12 steps, x prefetched one step ahead ----
    const float* xr = X + (size_t)rr * (TT * 2);
    float2 xt = *(const float2*)xr;
    for (int t = 0; t < TT; t++) {
        float2 xn = (t < TT - 1) ? *(const float2*)(xr + (t + 1) * 2) : xt;
        gru_step(sW, sGC, sH, tid, h2, xt.x, xt.y);
        xt = xn;
    }
    float lv = xt.x;   // last observed feature-0 value

    // ---- restage with decoder weights ----
    __syncthreads();
    {
        const float4* g4 = (const float4*)(dWhh + (size_t)c * GG * HH);
        float4* s4 = (float4*)sW;
        for (int i = tid; i < GG * HH / 4; i += BT) s4[i] = g4[i];
        for (int g = tid; g < GG; g += BT) {
            sGC[g*4+0] = dWih[c*GG + g];
            sGC[g*4+1] = 0.0f;
            sGC[g*4+2] = dbih[c*GG + g];
            sGC[g*4+3] = dbhh[c*GG + g];
        }
        for (int k = tid; k < HH; k += BT) sLin[k] = linW[c*HH + k];
        if (tid == 0) sLin[64] = linb[c];
    }
    __syncthreads();
    const float lb = sLin[64];

    // ---- decoder: 12 steps, lin projection feeds back as input ----
    for (int t = 0; t < TT; t++) {
        gru_step(sW, sGC, sH, tid, h2, lv, 0.0f);
        u64 acc = pk(0.f, 0.f);
        const float4* lw = (const float4*)sLin;
        #pragma unroll
        for (int kk = 0; kk < 16; kk++) {
            float4 w = lw[kk];
            fma2(acc, pk(w.x, w.y), h2[2*kk]);
            fma2(acc, pk(w.z, w.w), h2[2*kk+1]);
        }
        float2 af = unpk(acc);
        float value = af.x + af.y + lb;
        if (valid) g_vals[(r * TT + t) * CC + c] = value;
        lv = value;
    }
}

// out[b,n,t] = sum_c vals[b,n,t,c] * softmax(embed[n])[c]
extern "C" __global__ void mix_kernel(const float* __restrict__ embed,
                                      float* __restrict__ out)
{
    int i = blockIdx.x * blockDim.x + threadIdx.x;   // i = r*12 + t
    if (i >= BNR * TT) return;
    int n = (i / TT) % NN;
    const float* e = embed + n * CC;
    float m = e[0];
    #pragma unroll
    for (int cc = 1; cc < CC; cc++) m = fmaxf(m, e[cc]);
    const float* v = g_vals + i * CC;
    float s = 0.0f, acc = 0.0f;
    #pragma unroll
    for (int cc = 0; cc < CC; cc++) {
        float w = __expf(e[cc] - m);
        s += w;
        acc += v[cc] * w;
    }
    out[i] = __fdividef(acc, s);
}

extern "C" void kernel_launch(void* const* d_in, const int* in_sizes, int n_in,
                              void* d_out, int out_size)
{
    // metadata order: A, X, enc_Wih, enc_Whh, enc_bih, enc_bhh,
    //                 dec_Wih, dec_Whh, dec_bih, dec_bhh, lin_W, lin_b, embed
    const float* X     = (const float*)d_in[1];
    const float* eWih  = (const float*)d_in[2];
    const float* eWhh  = (const float*)d_in[3];
    const float* ebih  = (const float*)d_in[4];
    const float* ebhh  = (const float*)d_in[5];
    const float* dWih  = (const float*)d_in[6];
    const float* dWhh  = (const float*)d_in[7];
    const float* dbih  = (const float*)d_in[8];
    const float* dbhh  = (const float*)d_in[9];
    const float* linW  = (const float*)d_in[10];
    const float* linb  = (const float*)d_in[11];
    const float* embed = (const float*)d_in[12];
    float* out = (float*)d_out;

    const int smem_bytes = (13124 + HH * BT) * (int)sizeof(float);  // 85264 B
    cudaFuncSetAttribute((const void*)rnn_kernel,
                         cudaFuncAttributeMaxDynamicSharedMemorySize, smem_bytes);

    dim3 grid((BNR + BT - 1) / BT, CC);   // (82, 10)
    rnn_kernel<<<grid, BT, smem_bytes>>>(X, eWih, eWhh, ebih, ebhh,
                                         dWih, dWhh, dbih, dbhh, linW, linb);
    mix_kernel<<<(BNR * TT + 255) / 256, 256>>>(embed, out);
}

// round 4
// speedup vs baseline: 2.8939x; 2.8929x over previous
#include <cuda_runtime.h>
#include <cuda_bf16.h>
#include <cstdint>

#define BT  128
#define HH  64
#define GG  192
#define TT  12
#define CC  10
#define NN  325
#define BB  32
#define BNR (BB*NN)

// ---- SMEM byte offsets ----
#define A_HI   0u        // h hi  bf16: 128 rows x 128B (SW128 swizzled)
#define A_LO   16384u    // h lo
#define W_HI   32768u    // Whh hi bf16: 192 rows x 128B
#define W_LO   57344u    // Whh lo
#define GC_O   81920u    // 192 x float4 {wih0, wih1, bih, bhh}
#define LIN_O  84992u    // 68 floats: lin_W(64) + lin_b
#define GH_O   85264u    // per-warp gh staging: 4 x 32 x 28 floats
#define GH_STR 28
#define SMEM_BYTES (85264 + 4*32*GH_STR*4)   // 99600

__device__ float g_vals[BNR * TT * CC];

// ------------------------- helpers -------------------------
__device__ __forceinline__ uint32_t smem_u32(const void* p) {
    uint32_t a;
    asm("{ .reg .u64 t; cvta.to.shared.u64 t, %1; cvt.u32.u64 %0, t; }"
        : "=r"(a) : "l"(p));
    return a;
}
__device__ __forceinline__ void ldsm4(uint32_t* r, uint32_t addr) {
    asm volatile("ldmatrix.sync.aligned.m8n8.x4.shared.b16 {%0,%1,%2,%3}, [%4];"
                 : "=r"(r[0]), "=r"(r[1]), "=r"(r[2]), "=r"(r[3]) : "r"(addr));
}
__device__ __forceinline__ void hmma(float* d, const uint32_t* a,
                                     uint32_t b0, uint32_t b1) {
    asm volatile(
        "mma.sync.aligned.m16n8k16.row.col.f32.bf16.bf16.f32 "
        "{%0,%1,%2,%3}, {%4,%5,%6,%7}, {%8,%9}, {%0,%1,%2,%3};"
        : "+f"(d[0]), "+f"(d[1]), "+f"(d[2]), "+f"(d[3])
        : "r"(a[0]), "r"(a[1]), "r"(a[2]), "r"(a[3]), "r"(b0), "r"(b1));
}
__device__ __forceinline__ void sts64f(uint32_t addr, float a, float b) {
    asm volatile("st.shared.v2.f32 [%0], {%1,%2};" :: "r"(addr), "f"(a), "f"(b)
                 : "memory");
}
__device__ __forceinline__ void sts128(uint32_t addr, uint32_t a, uint32_t b,
                                       uint32_t c, uint32_t d) {
    asm volatile("st.shared.v4.b32 [%0], {%1,%2,%3,%4};"
                 :: "r"(addr), "r"(a), "r"(b), "r"(c), "r"(d) : "memory");
}
__device__ __forceinline__ float4 lds128f(uint32_t addr) {
    float4 v;
    asm volatile("ld.shared.v4.f32 {%0,%1,%2,%3}, [%4];"
                 : "=f"(v.x), "=f"(v.y), "=f"(v.z), "=f"(v.w) : "r"(addr));
    return v;
}
__device__ __forceinline__ uint4 lds128u(uint32_t addr) {
    uint4 v;
    asm volatile("ld.shared.v4.b32 {%0,%1,%2,%3}, [%4];"
                 : "=r"(v.x), "=r"(v.y), "=r"(v.z), "=r"(v.w) : "r"(addr));
    return v;
}
__device__ __forceinline__ float2 bf2f(uint32_t u) {
    __nv_bfloat162 b = *(__nv_bfloat162*)&u;
    return __bfloat1622float2(b);
}
__device__ __forceinline__ uint32_t pack2bf(float a, float b) {
    __nv_bfloat16 x = __float2bfloat16(a), y = __float2bfloat16(b);
    return ((uint32_t)__bfloat16_as_ushort(y) << 16) | __bfloat16_as_ushort(x);
}

__device__ __forceinline__ float sigm(float x) {
    return __fdividef(1.0f, 1.0f + __expf(-x));
}
__device__ __forceinline__ float tanh_(float x) {
    return __fmaf_rn(2.0f, sigm(2.0f * x), -1.0f);
}

// stage Whh (192x64 fp32) as bf16 hi/lo SW128-swizzled tiles
__device__ __forceinline__ void stage_whh(char* smem, const float* Wc, int tid) {
    for (int idx = tid; idx < GG * HH; idx += BT) {
        int g = idx >> 6, k = idx & 63;
        float w = Wc[idx];
        __nv_bfloat16 bh = __float2bfloat16(w);
        __nv_bfloat16 bl = __float2bfloat16(w - __bfloat162float(bh));
        uint32_t off = (uint32_t)g * 128u + (uint32_t)k * 2u;
        uint32_t sw = off ^ ((off >> 3) & 0x70);
        *(__nv_bfloat16*)(smem + W_HI + sw) = bh;
        *(__nv_bfloat16*)(smem + W_LO + sw) = bl;
    }
}

// 24 HMMA: acc[g][mt] += A[mt][kt] * B[g][kt]
__device__ __forceinline__ void mma_block(float (&acc)[3][2][4],
                                          const uint32_t (&A)[2][4][4],
                                          const uint32_t (&B)[3][8]) {
    #pragma unroll
    for (int g = 0; g < 3; g++)
        #pragma unroll
        for (int mt = 0; mt < 2; mt++)
            #pragma unroll
            for (int kt = 0; kt < 4; kt++) {
                int bi = (kt >> 1) * 4 + (kt & 1) * 2;
                hmma(acc[g][mt], A[mt][kt], B[g][bi], B[g][bi + 1]);
            }
}

extern "C" __global__ void __launch_bounds__(BT, 2)
rnn_kernel(const float* __restrict__ X,
           const float* __restrict__ eWih, const float* __restrict__ eWhh,
           const float* __restrict__ ebih, const float* __restrict__ ebhh,
           const float* __restrict__ dWih, const float* __restrict__ dWhh,
           const float* __restrict__ dbih, const float* __restrict__ dbhh,
           const float* __restrict__ linW, const float* __restrict__ linb)
{
    extern __shared__ char smem[];
    const uint32_t sb = smem_u32(smem);
    float* sGC  = (float*)(smem + GC_O);
    float* sLin = (float*)(smem + LIN_O);

    const int tid  = threadIdx.x;
    const int lane = tid & 31;
    const int w    = tid >> 5;
    const int c    = blockIdx.y;
    const int r    = blockIdx.x * BT + tid;
    const bool valid = (r < BNR);
    const int rr = valid ? r : (BNR - 1);

    // ---- stage encoder weights ----
    stage_whh(smem, eWhh + (size_t)c * GG * HH, tid);
    for (int g = tid; g < GG; g += BT) {
        sGC[g*4+0] = eWih[c*GG*2 + g*2];
        sGC[g*4+1] = eWih[c*GG*2 + g*2 + 1];
        sGC[g*4+2] = ebih[c*GG + g];
        sGC[g*4+3] = ebhh[c*GG + g];
    }
    for (int i = tid; i < 8192; i += BT) ((uint32_t*)(smem + A_HI))[i] = 0u;
    __syncthreads();

    // ---- per-lane ldmatrix address constants ----
    const int rb = lane & 15;
    const uint32_t aBase0 = sb + A_HI + (uint32_t)(w*32 + rb) * 128u;  // mt=0
    const uint32_t aBase1 = aBase0 + 16u*128u;
    const uint32_t akh  = ((uint32_t)lane >> 4) * 16u;
    const uint32_t axor = ((uint32_t)(rb & 7)) << 4;
    uint32_t akoff[4];
    #pragma unroll
    for (int kt = 0; kt < 4; kt++) akoff[kt] = ((uint32_t)kt*32u + akh) ^ axor;

    const uint32_t bg    = lane & 7;
    const uint32_t bkoff = ((uint32_t)lane >> 3) * 16u;
    const uint32_t bxor  = bg << 4;
    const uint32_t bk0 = (0u  + bkoff) ^ bxor;   // ktp 0
    const uint32_t bk1 = (64u + bkoff) ^ bxor;   // ktp 1
    const uint32_t bRow = bg * 128u;

    const uint32_t hxor = ((uint32_t)(tid & 7)) << 4;
    const uint32_t hAddrHi = sb + A_HI + (uint32_t)tid * 128u;

    const uint32_t ghW  = sb + GH_O + (uint32_t)w * (32u*GH_STR*4u);  // warp store base
    const uint32_t ghRd = ghW + (uint32_t)lane * (GH_STR*4u);         // my-row read base
    const float4* gc4 = (const float4*)sGC;

    const float* xr = X + (size_t)rr * (TT * 2);
    float lv = 0.0f;

    #pragma unroll 1
    for (int t = 0; t < 2 * TT; t++) {
        float x0, x1;
        if (t < TT) { x0 = xr[2*t]; x1 = xr[2*t + 1]; }
        else        { x0 = lv;      x1 = 0.0f; }

        if (t == TT) {   // restage decoder weights
            __syncthreads();
            stage_whh(smem, dWhh + (size_t)c * GG * HH, tid);
            for (int g = tid; g < GG; g += BT) {
                sGC[g*4+0] = dWih[c*GG + g];
                sGC[g*4+1] = 0.0f;
                sGC[g*4+2] = dbih[c*GG + g];
                sGC[g*4+3] = dbhh[c*GG + g];
            }
            for (int k = tid; k < HH; k += BT) sLin[k] = linW[c*HH + k];
            if (tid == 0) sLin[64] = linb[c];
            __syncthreads();
        }

        __syncwarp();   // prior step's h stores visible to ldmatrix

        // load this warp's A fragments (h hi/lo), resident for all chunks
        uint32_t Ah[2][4][4], Al[2][4][4];
        #pragma unroll
        for (int kt = 0; kt < 4; kt++) {
            ldsm4(Ah[0][kt], aBase0 + akoff[kt]);
            ldsm4(Ah[1][kt], aBase1 + akoff[kt]);
            ldsm4(Al[0][kt], aBase0 + 16384u + akoff[kt]);
            ldsm4(Al[1][kt], aBase1 + 16384u + akoff[kt]);
        }

        float v = 0.0f;

        #pragma unroll 1
        for (int ch = 0; ch < 8; ch++) {
            float acc[3][2][4];
            #pragma unroll
            for (int g = 0; g < 3; g++)
                #pragma unroll
                for (int mt = 0; mt < 2; mt++)
                    #pragma unroll
                    for (int q = 0; q < 4; q++) acc[g][mt][q] = 0.0f;

            // B tiles: gate rows ntb = g*64 + ch*8
            uint32_t B0[3][8];
            #pragma unroll
            for (int g = 0; g < 3; g++) {
                uint32_t wb = sb + W_HI + (uint32_t)(g*64 + ch*8) * 128u + bRow;
                ldsm4(&B0[g][0], wb + bk0);
                ldsm4(&B0[g][4], wb + bk1);
            }
            mma_block(acc, Ah, B0);   // P1: Ah x Bh
            mma_block(acc, Al, B0);   // P3: Al x Bh
            #pragma unroll
            for (int g = 0; g < 3; g++) {
                uint32_t wb = sb + W_LO + (uint32_t)(g*64 + ch*8) * 128u + bRow;
                ldsm4(&B0[g][0], wb + bk0);
                ldsm4(&B0[g][4], wb + bk1);
            }
            mma_block(acc, Ah, B0);   // P2: Ah x Bl

            __syncwarp();   // previous chunk's epilogue reads done
            // scatter fragments into per-warp gh buffer [row(32)][28]
            #pragma unroll
            for (int g = 0; g < 3; g++)
                #pragma unroll
                for (int mt = 0; mt < 2; mt++) {
                    int r0 = mt*16 + (lane >> 2);
                    int ci = g*8 + 2*(lane & 3);
                    sts64f(ghW + (uint32_t)(r0*GH_STR + ci)*4u,
                           acc[g][mt][0], acc[g][mt][1]);
                    sts64f(ghW + (uint32_t)((r0+8)*GH_STR + ci)*4u,
                           acc[g][mt][2], acc[g][mt][3]);
                }
            __syncwarp();

            // ---- epilogue: thread = row, 8 hidden units of this chunk ----
            uint32_t hOff = ((uint32_t)(ch*16)) ^ hxor;
            uint4 hh = lds128u(hAddrHi + hOff);
            uint4 hl = lds128u(hAddrHi + 16384u + hOff);
            float hold[8];
            {
                float2 a, b;
                a = bf2f(hh.x); b = bf2f(hl.x); hold[0]=a.x+b.x; hold[1]=a.y+b.y;
                a = bf2f(hh.y); b = bf2f(hl.y); hold[2]=a.x+b.x; hold[3]=a.y+b.y;
                a = bf2f(hh.z); b = bf2f(hl.z); hold[4]=a.x+b.x; hold[5]=a.y+b.y;
                a = bf2f(hh.w); b = bf2f(hl.w); hold[6]=a.x+b.x; hold[7]=a.y+b.y;
            }
            float GR[8], GZ[8], GN[8];
            *(float4*)&GR[0] = lds128f(ghRd);        *(float4*)&GR[4] = lds128f(ghRd + 16);
            *(float4*)&GZ[0] = lds128f(ghRd + 32);   *(float4*)&GZ[4] = lds128f(ghRd + 48);
            *(float4*)&GN[0] = lds128f(ghRd + 64);   *(float4*)&GN[4] = lds128f(ghRd + 80);

            float hn[8];
            #pragma unroll
            for (int u = 0; u < 8; u++) {
                int j = ch*8 + u;
                float4 cr = gc4[j], cz = gc4[j+64], cn = gc4[j+128];
                float gir = fmaf(cr.x, x0, fmaf(cr.y, x1, cr.z));
                float giz = fmaf(cz.x, x0, fmaf(cz.y, x1, cz.z));
                float gin = fmaf(cn.x, x0, fmaf(cn.y, x1, cn.z));
                float rg = sigm(gir + GR[u] + cr.w);
                float zg = sigm(giz + GZ[u] + cz.w);
                float ng = tanh_(fmaf(rg, GN[u] + cn.w, gin));
                hn[u] = fmaf(zg, hold[u] - ng, ng);
            }
            // split & store new h (bf16 hi/lo) back into A tiles
            uint32_t ph[4], pl[4];
            #pragma unroll
            for (int q = 0; q < 4; q++) {
                float a = hn[2*q], b = hn[2*q+1];
                __nv_bfloat16 ahb = __float2bfloat16(a), bhb = __float2bfloat16(b);
                ph[q] = ((uint32_t)__bfloat16_as_ushort(bhb) << 16)
                      |  __bfloat16_as_ushort(ahb);
                pl[q] = pack2bf(a - __bfloat162float(ahb), b - __bfloat162float(bhb));
            }
            sts128(hAddrHi + hOff,          ph[0], ph[1], ph[2], ph[3]);
            sts128(hAddrHi + 16384u + hOff, pl[0], pl[1], pl[2], pl[3]);

            if (t >= TT) {
                float4 L0 = lds128f(sb + LIN_O + (uint32_t)(ch*32));
                float4 L1 = lds128f(sb + LIN_O + (uint32_t)(ch*32) + 16u);
                v = fmaf(hn[0], L0.x, v); v = fmaf(hn[1], L0.y, v);
                v = fmaf(hn[2], L0.z, v); v = fmaf(hn[3], L0.w, v);
                v = fmaf(hn[4], L1.x, v); v = fmaf(hn[5], L1.y, v);
                v = fmaf(hn[6], L1.z, v); v = fmaf(hn[7], L1.w, v);
            }
        }

        if (t >= TT) {
            v += sLin[64];
            if (valid) g_vals[(r * TT + (t - TT)) * CC + c] = v;
            lv = v;
        }
        if (t == TT - 1) lv = x0;
    }
}

// out[b,n,t] = sum_c vals[b,n,t,c] * softmax(embed[n])[c]
extern "C" __global__ void mix_kernel(const float* __restrict__ embed,
                                      float* __restrict__ out)
{
    int i = blockIdx.x * blockDim.x + threadIdx.x;   // i = r*12 + t
    if (i >= BNR * TT) return;
    int n = (i / TT) % NN;
    const float* e = embed + n * CC;
    float m = e[0];
    #pragma unroll
    for (int cc = 1; cc < CC; cc++) m = fmaxf(m, e[cc]);
    const float* v = g_vals + i * CC;
    float s = 0.0f, acc = 0.0f;
    #pragma unroll
    for (int cc = 0; cc < CC; cc++) {
        float ww = __expf(e[cc] - m);
        s += ww;
        acc += v[cc] * ww;
    }
    out[i] = __fdividef(acc, s);
}

extern "C" void kernel_launch(void* const* d_in, const int* in_sizes, int n_in,
                              void* d_out, int out_size)
{
    // metadata order: A, X, enc_Wih, enc_Whh, enc_bih, enc_bhh,
    //                 dec_Wih, dec_Whh, dec_bih, dec_bhh, lin_W, lin_b, embed
    const float* X     = (const float*)d_in[1];
    const float* eWih  = (const float*)d_in[2];
    const float* eWhh  = (const float*)d_in[3];
    const float* ebih  = (const float*)d_in[4];
    const float* ebhh  = (const float*)d_in[5];
    const float* dWih  = (const float*)d_in[6];
    const float* dWhh  = (const float*)d_in[7];
    const float* dbih  = (const float*)d_in[8];
    const float* dbhh  = (const float*)d_in[9];
    const float* linW  = (const float*)d_in[10];
    const float* linb  = (const float*)d_in[11];
    const float* embed = (const float*)d_in[12];
    float* out = (float*)d_out;

    cudaFuncSetAttribute((const void*)rnn_kernel,
                         cudaFuncAttributeMaxDynamicSharedMemorySize, SMEM_BYTES);

    dim3 grid((BNR + BT - 1) / BT, CC);   // (82, 10)
    rnn_kernel<<<grid, BT, SMEM_BYTES>>>(X, eWih, eWhh, ebih, ebhh,
                                         dWih, dWhh, dbih, dbhh, linW, linb);
    mix_kernel<<<(BNR * TT + 255) / 256, 256>>>(embed, out);
}

// round 5
// speedup vs baseline: 4.1036x; 1.4180x over previous
#include <cuda_runtime.h>
#include <cuda_fp16.h>
#include <cstdint>

#define BT  128
#define HH  64
#define GG  192
#define TT  12
#define CC  10
#define NN  325
#define BB  32
#define BNR (BB*NN)

// ---- SMEM byte offsets ----
#define A_T    0u        // h fp16: 128 rows x 128B (SW128 swizzled)
#define W_T    16384u    // Whh fp16: 192 rows x 128B
#define GC_O   40960u    // 192 x float4 {wih0, wih1, bih, bhh}
#define LIN_O  44032u    // 68 floats: lin_W(64) + lin_b
#define GH_O   44304u    // per-warp gh staging: 4 x 32 x 28 floats
#define GH_STR 28
#define SMEM_BYTES (44304 + 4*32*GH_STR*4)   // 58640

__device__ float g_vals[BNR * TT * CC];

// ------------------------- helpers -------------------------
__device__ __forceinline__ uint32_t smem_u32(const void* p) {
    uint32_t a;
    asm("{ .reg .u64 t; cvta.to.shared.u64 t, %1; cvt.u32.u64 %0, t; }"
        : "=r"(a) : "l"(p));
    return a;
}
__device__ __forceinline__ void ldsm4(uint32_t* r, uint32_t addr) {
    asm volatile("ldmatrix.sync.aligned.m8n8.x4.shared.b16 {%0,%1,%2,%3}, [%4];"
                 : "=r"(r[0]), "=r"(r[1]), "=r"(r[2]), "=r"(r[3]) : "r"(addr));
}
__device__ __forceinline__ void hmma(float* d, const uint32_t* a,
                                     uint32_t b0, uint32_t b1) {
    asm volatile(
        "mma.sync.aligned.m16n8k16.row.col.f32.f16.f16.f32 "
        "{%0,%1,%2,%3}, {%4,%5,%6,%7}, {%8,%9}, {%0,%1,%2,%3};"
        : "+f"(d[0]), "+f"(d[1]), "+f"(d[2]), "+f"(d[3])
        : "r"(a[0]), "r"(a[1]), "r"(a[2]), "r"(a[3]), "r"(b0), "r"(b1));
}
__device__ __forceinline__ void sts64f(uint32_t addr, float a, float b) {
    asm volatile("st.shared.v2.f32 [%0], {%1,%2};" :: "r"(addr), "f"(a), "f"(b)
                 : "memory");
}
__device__ __forceinline__ void sts128(uint32_t addr, uint32_t a, uint32_t b,
                                       uint32_t c, uint32_t d) {
    asm volatile("st.shared.v4.b32 [%0], {%1,%2,%3,%4};"
                 :: "r"(addr), "r"(a), "r"(b), "r"(c), "r"(d) : "memory");
}
__device__ __forceinline__ float4 lds128f(uint32_t addr) {
    float4 v;
    asm volatile("ld.shared.v4.f32 {%0,%1,%2,%3}, [%4];"
                 : "=f"(v.x), "=f"(v.y), "=f"(v.z), "=f"(v.w) : "r"(addr));
    return v;
}
__device__ __forceinline__ uint32_t pack2h(float a, float b) {
    __half2 h2 = __floats2half2_rn(a, b);
    return *(uint32_t*)&h2;
}

__device__ __forceinline__ float sigm(float x) {
    return __fdividef(1.0f, 1.0f + __expf(-x));
}
__device__ __forceinline__ float tanh_(float x) {
    return __fmaf_rn(2.0f, sigm(2.0f * x), -1.0f);
}

// stage Whh (192x64 fp32) as a single fp16 SW128-swizzled tile
__device__ __forceinline__ void stage_whh(char* smem, const float* Wc, int tid) {
    for (int idx = tid; idx < GG * HH; idx += BT) {
        int g = idx >> 6, k = idx & 63;
        uint32_t off = (uint32_t)g * 128u + (uint32_t)k * 2u;
        uint32_t sw = off ^ ((off >> 3) & 0x70);
        *(__half*)(smem + W_T + sw) = __float2half_rn(Wc[idx]);
    }
}

extern "C" __global__ void __launch_bounds__(BT, 2)
rnn_kernel(const float* __restrict__ X,
           const float* __restrict__ eWih, const float* __restrict__ eWhh,
           const float* __restrict__ ebih, const float* __restrict__ ebhh,
           const float* __restrict__ dWih, const float* __restrict__ dWhh,
           const float* __restrict__ dbih, const float* __restrict__ dbhh,
           const float* __restrict__ linW, const float* __restrict__ linb)
{
    extern __shared__ char smem[];
    const uint32_t sb = smem_u32(smem);
    float* sGC  = (float*)(smem + GC_O);
    float* sLin = (float*)(smem + LIN_O);

    const int tid  = threadIdx.x;
    const int lane = tid & 31;
    const int w    = tid >> 5;
    const int c    = blockIdx.y;
    const int r    = blockIdx.x * BT + tid;
    const bool valid = (r < BNR);
    const int rr = valid ? r : (BNR - 1);

    // ---- stage encoder weights ----
    stage_whh(smem, eWhh + (size_t)c * GG * HH, tid);
    for (int g = tid; g < GG; g += BT) {
        sGC[g*4+0] = eWih[c*GG*2 + g*2];
        sGC[g*4+1] = eWih[c*GG*2 + g*2 + 1];
        sGC[g*4+2] = ebih[c*GG + g];
        sGC[g*4+3] = ebhh[c*GG + g];
    }
    for (int i = tid; i < 4096; i += BT) ((uint32_t*)(smem + A_T))[i] = 0u;
    __syncthreads();

    // ---- per-lane ldmatrix address constants ----
    const int rb = lane & 15;
    const uint32_t aBase0 = sb + A_T + (uint32_t)(w*32 + rb) * 128u;  // mt=0
    const uint32_t aBase1 = aBase0 + 16u*128u;
    const uint32_t akh  = ((uint32_t)lane >> 4) * 16u;
    const uint32_t axor = ((uint32_t)(rb & 7)) << 4;
    uint32_t akoff[4];
    #pragma unroll
    for (int kt = 0; kt < 4; kt++) akoff[kt] = ((uint32_t)kt*32u + akh) ^ axor;

    const uint32_t bg    = lane & 7;
    const uint32_t bkoff = ((uint32_t)lane >> 3) * 16u;
    const uint32_t bxor  = bg << 4;
    const uint32_t bk0 = (0u  + bkoff) ^ bxor;
    const uint32_t bk1 = (64u + bkoff) ^ bxor;
    const uint32_t bRow = bg * 128u;

    const uint32_t hxor = ((uint32_t)(tid & 7)) << 4;
    const uint32_t hAddr = sb + A_T + (uint32_t)tid * 128u;

    const uint32_t ghW  = sb + GH_O + (uint32_t)w * (32u*GH_STR*4u);
    const uint32_t ghRd = ghW + (uint32_t)lane * (GH_STR*4u);
    const float4* gc4 = (const float4*)sGC;

    // exact fp32 hidden state, register-resident (thread = row)
    float h[HH];
    #pragma unroll
    for (int j = 0; j < HH; j++) h[j] = 0.0f;

    const float* xr = X + (size_t)rr * (TT * 2);
    float lv = 0.0f;

    #pragma unroll 1
    for (int t = 0; t < 2 * TT; t++) {
        float x0, x1;
        if (t < TT) { x0 = xr[2*t]; x1 = xr[2*t + 1]; }
        else        { x0 = lv;      x1 = 0.0f; }

        if (t == TT) {   // restage decoder weights
            __syncthreads();
            stage_whh(smem, dWhh + (size_t)c * GG * HH, tid);
            for (int g = tid; g < GG; g += BT) {
                sGC[g*4+0] = dWih[c*GG + g];
                sGC[g*4+1] = 0.0f;
                sGC[g*4+2] = dbih[c*GG + g];
                sGC[g*4+3] = dbhh[c*GG + g];
            }
            for (int k = tid; k < HH; k += BT) sLin[k] = linW[c*HH + k];
            if (tid == 0) sLin[64] = linb[c];
            __syncthreads();
        }

        __syncwarp();   // prior step's h stores visible to ldmatrix

        // load this warp's A fragments (h fp16)
        uint32_t Ah[2][4][4];
        #pragma unroll
        for (int kt = 0; kt < 4; kt++) {
            ldsm4(Ah[0][kt], aBase0 + akoff[kt]);
            ldsm4(Ah[1][kt], aBase1 + akoff[kt]);
        }

        float v = 0.0f;

        #pragma unroll
        for (int ch = 0; ch < 8; ch++) {
            float acc[3][2][4];
            #pragma unroll
            for (int g = 0; g < 3; g++)
                #pragma unroll
                for (int mt = 0; mt < 2; mt++)
                    #pragma unroll
                    for (int q = 0; q < 4; q++) acc[g][mt][q] = 0.0f;

            // B tiles: gate rows g*64 + ch*8, single fp16 pass
            uint32_t B0[3][8];
            #pragma unroll
            for (int g = 0; g < 3; g++) {
                uint32_t wb = sb + W_T + (uint32_t)(g*64 + ch*8) * 128u + bRow;
                ldsm4(&B0[g][0], wb + bk0);
                ldsm4(&B0[g][4], wb + bk1);
            }
            #pragma unroll
            for (int g = 0; g < 3; g++)
                #pragma unroll
                for (int mt = 0; mt < 2; mt++)
                    #pragma unroll
                    for (int kt = 0; kt < 4; kt++) {
                        int bi = (kt >> 1) * 4 + (kt & 1) * 2;
                        hmma(acc[g][mt], Ah[mt][kt], B0[g][bi], B0[g][bi + 1]);
                    }

            __syncwarp();   // previous chunk's epilogue reads done
            #pragma unroll
            for (int g = 0; g < 3; g++)
                #pragma unroll
                for (int mt = 0; mt < 2; mt++) {
                    int r0 = mt*16 + (lane >> 2);
                    int ci = g*8 + 2*(lane & 3);
                    sts64f(ghW + (uint32_t)(r0*GH_STR + ci)*4u,
                           acc[g][mt][0], acc[g][mt][1]);
                    sts64f(ghW + (uint32_t)((r0+8)*GH_STR + ci)*4u,
                           acc[g][mt][2], acc[g][mt][3]);
                }
            __syncwarp();

            // ---- epilogue: thread = row, 8 hidden units of this chunk ----
            float GR[8], GZ[8], GN[8];
            *(float4*)&GR[0] = lds128f(ghRd);        *(float4*)&GR[4] = lds128f(ghRd + 16);
            *(float4*)&GZ[0] = lds128f(ghRd + 32);   *(float4*)&GZ[4] = lds128f(ghRd + 48);
            *(float4*)&GN[0] = lds128f(ghRd + 64);   *(float4*)&GN[4] = lds128f(ghRd + 80);

            float hn[8];
            #pragma unroll
            for (int u = 0; u < 8; u++) {
                const int j = ch*8 + u;
                float4 cr = gc4[j], cz = gc4[j+64], cn = gc4[j+128];
                float gir = fmaf(cr.x, x0, fmaf(cr.y, x1, cr.z));
                float giz = fmaf(cz.x, x0, fmaf(cz.y, x1, cz.z));
                float gin = fmaf(cn.x, x0, fmaf(cn.y, x1, cn.z));
                float rg = sigm(gir + GR[u] + cr.w);
                float zg = sigm(giz + GZ[u] + cz.w);
                float ng = tanh_(fmaf(rg, GN[u] + cn.w, gin));
                hn[u] = fmaf(zg, h[j] - ng, ng);
                h[j] = hn[u];
            }
            // store new h (fp16) back into A tile
            uint32_t ph[4];
            #pragma unroll
            for (int q = 0; q < 4; q++) ph[q] = pack2h(hn[2*q], hn[2*q+1]);
            uint32_t hOff = ((uint32_t)(ch*16)) ^ hxor;
            sts128(hAddr + hOff, ph[0], ph[1], ph[2], ph[3]);

            if (t >= TT) {
                float4 L0 = lds128f(sb + LIN_O + (uint32_t)(ch*32));
                float4 L1 = lds128f(sb + LIN_O + (uint32_t)(ch*32) + 16u);
                v = fmaf(hn[0], L0.x, v); v = fmaf(hn[1], L0.y, v);
                v = fmaf(hn[2], L0.z, v); v = fmaf(hn[3], L0.w, v);
                v = fmaf(hn[4], L1.x, v); v = fmaf(hn[5], L1.y, v);
                v = fmaf(hn[6], L1.z, v); v = fmaf(hn[7], L1.w, v);
            }
        }

        if (t >= TT) {
            v += sLin[64];
            if (valid) g_vals[(r * TT + (t - TT)) * CC + c] = v;
            lv = v;
        }
        if (t == TT - 1) lv = x0;
    }
}

// out[b,n,t] = sum_c vals[b,n,t,c] * softmax(embed[n])[c]
extern "C" __global__ void mix_kernel(const float* __restrict__ embed,
                                      float* __restrict__ out)
{
    int i = blockIdx.x * blockDim.x + threadIdx.x;   // i = r*12 + t
    if (i >= BNR * TT) return;
    int n = (i / TT) % NN;
    const float* e = embed + n * CC;
    float m = e[0];
    #pragma unroll
    for (int cc = 1; cc < CC; cc++) m = fmaxf(m, e[cc]);
    const float* v = g_vals + i * CC;
    float s = 0.0f, acc = 0.0f;
    #pragma unroll
    for (int cc = 0; cc < CC; cc++) {
        float ww = __expf(e[cc] - m);
        s += ww;
        acc += v[cc] * ww;
    }
    out[i] = __fdividef(acc, s);
}

extern "C" void kernel_launch(void* const* d_in, const int* in_sizes, int n_in,
                              void* d_out, int out_size)
{
    // metadata order: A, X, enc_Wih, enc_Whh, enc_bih, enc_bhh,
    //                 dec_Wih, dec_Whh, dec_bih, dec_bhh, lin_W, lin_b, embed
    const float* X     = (const float*)d_in[1];
    const float* eWih  = (const float*)d_in[2];
    const float* eWhh  = (const float*)d_in[3];
    const float* ebih  = (const float*)d_in[4];
    const float* ebhh  = (const float*)d_in[5];
    const float* dWih  = (const float*)d_in[6];
    const float* dWhh  = (const float*)d_in[7];
    const float* dbih  = (const float*)d_in[8];
    const float* dbhh  = (const float*)d_in[9];
    const float* linW  = (const float*)d_in[10];
    const float* linb  = (const float*)d_in[11];
    const float* embed = (const float*)d_in[12];
    float* out = (float*)d_out;

    cudaFuncSetAttribute((const void*)rnn_kernel,
                         cudaFuncAttributeMaxDynamicSharedMemorySize, SMEM_BYTES);

    dim3 grid((BNR + BT - 1) / BT, CC);   // (82, 10)
    rnn_kernel<<<grid, BT, SMEM_BYTES>>>(X, eWih, eWhh, ebih, ebhh,
                                         dWih, dWhh, dbih, dbhh, linW, linb);
    mix_kernel<<<(BNR * TT + 255) / 256, 256>>>(embed, out);
}

// round 6
// speedup vs baseline: 4.2000x; 1.0235x over previous
#include <cuda_runtime.h>
#include <cuda_fp16.h>
#include <cstdint>

#define BT  128
#define HH  64
#define GG  192
#define TT  12
#define CC  10
#define NN  325
#define BB  32
#define BNR (BB*NN)

// ---- SMEM byte offsets ----
#define A_T    0u        // h fp16: 128 rows x 128B (SW128 swizzled)
#define W_T    16384u    // Whh fp16: 192 rows x 128B
#define GC_O   40960u    // 192 x float4 {wih0, wih1, bih, bhh}
#define LIN_O  44032u    // 68 floats: lin_W(64) + lin_b
#define GH_O   44304u    // per-warp gh staging: 4 x 32 x 28 floats
#define GH_STR 28
#define SMEM_BYTES (44304 + 4*32*GH_STR*4)   // 58640

__device__ float g_vals[BNR * TT * CC];

// ------------------------- helpers -------------------------
__device__ __forceinline__ uint32_t smem_u32(const void* p) {
    uint32_t a;
    asm("{ .reg .u64 t; cvta.to.shared.u64 t, %1; cvt.u32.u64 %0, t; }"
        : "=r"(a) : "l"(p));
    return a;
}
__device__ __forceinline__ void ldsm4(uint32_t* r, uint32_t addr) {
    asm volatile("ldmatrix.sync.aligned.m8n8.x4.shared.b16 {%0,%1,%2,%3}, [%4];"
                 : "=r"(r[0]), "=r"(r[1]), "=r"(r[2]), "=r"(r[3]) : "r"(addr));
}
__device__ __forceinline__ void hmma(float* d, const uint32_t* a,
                                     uint32_t b0, uint32_t b1) {
    asm volatile(
        "mma.sync.aligned.m16n8k16.row.col.f32.f16.f16.f32 "
        "{%0,%1,%2,%3}, {%4,%5,%6,%7}, {%8,%9}, {%0,%1,%2,%3};"
        : "+f"(d[0]), "+f"(d[1]), "+f"(d[2]), "+f"(d[3])
        : "r"(a[0]), "r"(a[1]), "r"(a[2]), "r"(a[3]), "r"(b0), "r"(b1));
}
__device__ __forceinline__ void sts64f(uint32_t addr, float a, float b) {
    asm volatile("st.shared.v2.f32 [%0], {%1,%2};" :: "r"(addr), "f"(a), "f"(b)
                 : "memory");
}
__device__ __forceinline__ void sts128(uint32_t addr, uint32_t a, uint32_t b,
                                       uint32_t c, uint32_t d) {
    asm volatile("st.shared.v4.b32 [%0], {%1,%2,%3,%4};"
                 :: "r"(addr), "r"(a), "r"(b), "r"(c), "r"(d) : "memory");
}
__device__ __forceinline__ float4 lds128f(uint32_t addr) {
    float4 v;
    asm volatile("ld.shared.v4.f32 {%0,%1,%2,%3}, [%4];"
                 : "=f"(v.x), "=f"(v.y), "=f"(v.z), "=f"(v.w) : "r"(addr));
    return v;
}
__device__ __forceinline__ uint32_t pack2h(float a, float b) {
    __half2 h2 = __floats2half2_rn(a, b);
    return *(uint32_t*)&h2;
}

__device__ __forceinline__ float sigm(float x) {
    return __fdividef(1.0f, 1.0f + __expf(-x));
}
__device__ __forceinline__ float tanh_(float x) {
    return __fmaf_rn(2.0f, sigm(2.0f * x), -1.0f);
}

// stage Whh (192x64 fp32) as a single fp16 SW128-swizzled tile
__device__ __forceinline__ void stage_whh(char* smem, const float* Wc, int tid) {
    for (int idx = tid; idx < GG * HH; idx += BT) {
        int g = idx >> 6, k = idx & 63;
        uint32_t off = (uint32_t)g * 128u + (uint32_t)k * 2u;
        uint32_t sw = off ^ ((off >> 3) & 0x70);
        *(__half*)(smem + W_T + sw) = __float2half_rn(Wc[idx]);
    }
}

// load B tiles for chunk ch and issue its 24 HMMA into acc
__device__ __forceinline__ void issue_chunk(uint32_t sb, uint32_t bRow,
                                            uint32_t bk0, uint32_t bk1,
                                            const uint32_t (&Ah)[2][4][4],
                                            float (*acc)[2][4], int ch) {
    #pragma unroll
    for (int g = 0; g < 3; g++)
        #pragma unroll
        for (int mt = 0; mt < 2; mt++)
            #pragma unroll
            for (int q = 0; q < 4; q++) acc[g][mt][q] = 0.0f;

    uint32_t B0[3][8];
    #pragma unroll
    for (int g = 0; g < 3; g++) {
        uint32_t wb = sb + W_T + (uint32_t)(g*64 + ch*8) * 128u + bRow;
        ldsm4(&B0[g][0], wb + bk0);
        ldsm4(&B0[g][4], wb + bk1);
    }
    #pragma unroll
    for (int g = 0; g < 3; g++)
        #pragma unroll
        for (int mt = 0; mt < 2; mt++)
            #pragma unroll
            for (int kt = 0; kt < 4; kt++) {
                int bi = (kt >> 1) * 4 + (kt & 1) * 2;
                hmma(acc[g][mt], Ah[mt][kt], B0[g][bi], B0[g][bi + 1]);
            }
}

extern "C" __global__ void __launch_bounds__(BT, 2)
rnn_kernel(const float* __restrict__ X,
           const float* __restrict__ eWih, const float* __restrict__ eWhh,
           const float* __restrict__ ebih, const float* __restrict__ ebhh,
           const float* __restrict__ dWih, const float* __restrict__ dWhh,
           const float* __restrict__ dbih, const float* __restrict__ dbhh,
           const float* __restrict__ linW, const float* __restrict__ linb)
{
    extern __shared__ char smem[];
    const uint32_t sb = smem_u32(smem);
    float* sGC  = (float*)(smem + GC_O);
    float* sLin = (float*)(smem + LIN_O);

    const int tid  = threadIdx.x;
    const int lane = tid & 31;
    const int w    = tid >> 5;
    const int c    = blockIdx.y;
    const int r    = blockIdx.x * BT + tid;
    const bool valid = (r < BNR);
    const int rr = valid ? r : (BNR - 1);

    // ---- stage encoder weights ----
    stage_whh(smem, eWhh + (size_t)c * GG * HH, tid);
    for (int g = tid; g < GG; g += BT) {
        sGC[g*4+0] = eWih[c*GG*2 + g*2];
        sGC[g*4+1] = eWih[c*GG*2 + g*2 + 1];
        sGC[g*4+2] = ebih[c*GG + g];
        sGC[g*4+3] = ebhh[c*GG + g];
    }
    for (int i = tid; i < 4096; i += BT) ((uint32_t*)(smem + A_T))[i] = 0u;
    __syncthreads();

    // ---- per-lane ldmatrix address constants ----
    const int rb = lane & 15;
    const uint32_t aBase0 = sb + A_T + (uint32_t)(w*32 + rb) * 128u;  // mt=0
    const uint32_t aBase1 = aBase0 + 16u*128u;
    const uint32_t akh  = ((uint32_t)lane >> 4) * 16u;
    const uint32_t axor = ((uint32_t)(rb & 7)) << 4;
    uint32_t akoff[4];
    #pragma unroll
    for (int kt = 0; kt < 4; kt++) akoff[kt] = ((uint32_t)kt*32u + akh) ^ axor;

    const uint32_t bg    = lane & 7;
    const uint32_t bkoff = ((uint32_t)lane >> 3) * 16u;
    const uint32_t bxor  = bg << 4;
    const uint32_t bk0 = (0u  + bkoff) ^ bxor;
    const uint32_t bk1 = (64u + bkoff) ^ bxor;
    const uint32_t bRow = bg * 128u;

    const uint32_t hxor = ((uint32_t)(tid & 7)) << 4;
    const uint32_t hAddr = sb + A_T + (uint32_t)tid * 128u;

    const uint32_t ghW  = sb + GH_O + (uint32_t)w * (32u*GH_STR*4u);
    const uint32_t ghRd = ghW + (uint32_t)lane * (GH_STR*4u);
    const float4* gc4 = (const float4*)sGC;

    // exact fp32 hidden state, register-resident (thread = row)
    float h[HH];
    #pragma unroll
    for (int j = 0; j < HH; j++) h[j] = 0.0f;

    const float* xr = X + (size_t)rr * (TT * 2);
    float lv = 0.0f;

    #pragma unroll 1
    for (int t = 0; t < 2 * TT; t++) {
        float x0, x1;
        if (t < TT) { x0 = xr[2*t]; x1 = xr[2*t + 1]; }
        else        { x0 = lv;      x1 = 0.0f; }

        if (t == TT) {   // restage decoder weights
            __syncthreads();
            stage_whh(smem, dWhh + (size_t)c * GG * HH, tid);
            for (int g = tid; g < GG; g += BT) {
                sGC[g*4+0] = dWih[c*GG + g];
                sGC[g*4+1] = 0.0f;
                sGC[g*4+2] = dbih[c*GG + g];
                sGC[g*4+3] = dbhh[c*GG + g];
            }
            for (int k = tid; k < HH; k += BT) sLin[k] = linW[c*HH + k];
            if (tid == 0) sLin[64] = linb[c];
            __syncthreads();
        }

        __syncwarp();   // prior step's h stores visible to ldmatrix

        // load this warp's A fragments (h fp16)
        uint32_t Ah[2][4][4];
        #pragma unroll
        for (int kt = 0; kt < 4; kt++) {
            ldsm4(Ah[0][kt], aBase0 + akoff[kt]);
            ldsm4(Ah[1][kt], aBase1 + akoff[kt]);
        }

        float v = 0.0f;

        // ---- software-pipelined chunk loop (depth 2) ----
        float accbuf[2][3][2][4];
        issue_chunk(sb, bRow, bk0, bk1, Ah, accbuf[0], 0);

        #pragma unroll
        for (int ch = 0; ch < 8; ch++) {
            // issue next chunk's MMA before consuming this chunk's results
            if (ch < 7)
                issue_chunk(sb, bRow, bk0, bk1, Ah, accbuf[(ch + 1) & 1], ch + 1);

            float (*acc)[2][4] = accbuf[ch & 1];

            __syncwarp();   // previous chunk's gh-buffer reads done
            #pragma unroll
            for (int g = 0; g < 3; g++)
                #pragma unroll
                for (int mt = 0; mt < 2; mt++) {
                    int r0 = mt*16 + (lane >> 2);
                    int ci = g*8 + 2*(lane & 3);
                    sts64f(ghW + (uint32_t)(r0*GH_STR + ci)*4u,
                           acc[g][mt][0], acc[g][mt][1]);
                    sts64f(ghW + (uint32_t)((r0+8)*GH_STR + ci)*4u,
                           acc[g][mt][2], acc[g][mt][3]);
                }
            __syncwarp();

            // ---- epilogue: thread = row, 8 hidden units of this chunk ----
            float GR[8], GZ[8], GN[8];
            *(float4*)&GR[0] = lds128f(ghRd);        *(float4*)&GR[4] = lds128f(ghRd + 16);
            *(float4*)&GZ[0] = lds128f(ghRd + 32);   *(float4*)&GZ[4] = lds128f(ghRd + 48);
            *(float4*)&GN[0] = lds128f(ghRd + 64);   *(float4*)&GN[4] = lds128f(ghRd + 80);

            float hn[8];
            #pragma unroll
            for (int u = 0; u < 8; u++) {
                const int j = ch*8 + u;
                float4 cr = gc4[j], cz = gc4[j+64], cn = gc4[j+128];
                float gir = fmaf(cr.x, x0, fmaf(cr.y, x1, cr.z));
                float giz = fmaf(cz.x, x0, fmaf(cz.y, x1, cz.z));
                float gin = fmaf(cn.x, x0, fmaf(cn.y, x1, cn.z));
                float rg = sigm(gir + GR[u] + cr.w);
                float zg = sigm(giz + GZ[u] + cz.w);
                float ng = tanh_(fmaf(rg, GN[u] + cn.w, gin));
                hn[u] = fmaf(zg, h[j] - ng, ng);
                h[j] = hn[u];
            }
            // store new h (fp16) back into A tile
            uint32_t ph[4];
            #pragma unroll
            for (int q = 0; q < 4; q++) ph[q] = pack2h(hn[2*q], hn[2*q+1]);
            uint32_t hOff = ((uint32_t)(ch*16)) ^ hxor;
            sts128(hAddr + hOff, ph[0], ph[1], ph[2], ph[3]);

            if (t >= TT) {
                float4 L0 = lds128f(sb + LIN_O + (uint32_t)(ch*32));
                float4 L1 = lds128f(sb + LIN_O + (uint32_t)(ch*32) + 16u);
                v = fmaf(hn[0], L0.x, v); v = fmaf(hn[1], L0.y, v);
                v = fmaf(hn[2], L0.z, v); v = fmaf(hn[3], L0.w, v);
                v = fmaf(hn[4], L1.x, v); v = fmaf(hn[5], L1.y, v);
                v = fmaf(hn[6], L1.z, v); v = fmaf(hn[7], L1.w, v);
            }
        }

        if (t >= TT) {
            v += sLin[64];
            if (valid) g_vals[(r * TT + (t - TT)) * CC + c] = v;
            lv = v;
        }
        if (t == TT - 1) lv = x0;
    }
}

// out[b,n,t] = sum_c vals[b,n,t,c] * softmax(embed[n])[c]
extern "C" __global__ void mix_kernel(const float* __restrict__ embed,
                                      float* __restrict__ out)
{
    int i = blockIdx.x * blockDim.x + threadIdx.x;   // i = r*12 + t
    if (i >= BNR * TT) return;
    int n = (i / TT) % NN;
    const float* e = embed + n * CC;
    float m = e[0];
    #pragma unroll
    for (int cc = 1; cc < CC; cc++) m = fmaxf(m, e[cc]);
    const float* v = g_vals + i * CC;
    float s = 0.0f, acc = 0.0f;
    #pragma unroll
    for (int cc = 0; cc < CC; cc++) {
        float ww = __expf(e[cc] - m);
        s += ww;
        acc += v[cc] * ww;
    }
    out[i] = __fdividef(acc, s);
}

extern "C" void kernel_launch(void* const* d_in, const int* in_sizes, int n_in,
                              void* d_out, int out_size)
{
    // metadata order: A, X, enc_Wih, enc_Whh, enc_bih, enc_bhh,
    //                 dec_Wih, dec_Whh, dec_bih, dec_bhh, lin_W, lin_b, embed
    const float* X     = (const float*)d_in[1];
    const float* eWih  = (const float*)d_in[2];
    const float* eWhh  = (const float*)d_in[3];
    const float* ebih  = (const float*)d_in[4];
    const float* ebhh  = (const float*)d_in[5];
    const float* dWih  = (const float*)d_in[6];
    const float* dWhh  = (const float*)d_in[7];
    const float* dbih  = (const float*)d_in[8];
    const float* dbhh  = (const float*)d_in[9];
    const float* linW  = (const float*)d_in[10];
    const float* linb  = (const float*)d_in[11];
    const float* embed = (const float*)d_in[12];
    float* out = (float*)d_out;

    cudaFuncSetAttribute((const void*)rnn_kernel,
                         cudaFuncAttributeMaxDynamicSharedMemorySize, SMEM_BYTES);

    dim3 grid((BNR + BT - 1) / BT, CC);   // (82, 10)
    rnn_kernel<<<grid, BT, SMEM_BYTES>>>(X, eWih, eWhh, ebih, ebhh,
                                         dWih, dWhh, dbih, dbhh, linW, linb);
    mix_kernel<<<(BNR * TT + 255) / 256, 256>>>(embed, out);
}

// round 7
// speedup vs baseline: 5.5519x; 1.3219x over previous
#include <cuda_runtime.h>
#include <cuda_fp16.h>
#include <cstdint>

#define BT  128
#define HH  64
#define GG  192
#define TT  12
#define CC  10
#define NN  325
#define BB  32
#define BNR (BB*NN)

// ---- SMEM byte offsets ----
#define A_T    0u        // h fp16: 128 rows x 128B (SW128 swizzled)
#define W_T    16384u    // Whh fp16: 192 rows x 128B
#define CST_O  40960u    // 64 units x 12 floats {r: w0,w1,bsum,0 | z: w0,w1,bsum,0 | n: w0,w1,bin,bhn}
#define X_O    44032u    // 128 x float2 per-row input (x0,x1)
#define LIN_O  45056u    // 64 floats lin_W + lin_b
#define SMEM_BYTES 45568

__device__ float g_vals[BNR * TT * CC];

// ------------------------- helpers -------------------------
__device__ __forceinline__ uint32_t smem_u32(const void* p) {
    uint32_t a;
    asm("{ .reg .u64 t; cvta.to.shared.u64 t, %1; cvt.u32.u64 %0, t; }"
        : "=r"(a) : "l"(p));
    return a;
}
__device__ __forceinline__ void ldsm4(uint32_t* r, uint32_t addr) {
    asm volatile("ldmatrix.sync.aligned.m8n8.x4.shared.b16 {%0,%1,%2,%3}, [%4];"
                 : "=r"(r[0]), "=r"(r[1]), "=r"(r[2]), "=r"(r[3]) : "r"(addr));
}
__device__ __forceinline__ void hmma(float* d, const uint32_t* a,
                                     uint32_t b0, uint32_t b1) {
    asm volatile(
        "mma.sync.aligned.m16n8k16.row.col.f32.f16.f16.f32 "
        "{%0,%1,%2,%3}, {%4,%5,%6,%7}, {%8,%9}, {%0,%1,%2,%3};"
        : "+f"(d[0]), "+f"(d[1]), "+f"(d[2]), "+f"(d[3])
        : "r"(a[0]), "r"(a[1]), "r"(a[2]), "r"(a[3]), "r"(b0), "r"(b1));
}
__device__ __forceinline__ void sts32(uint32_t addr, uint32_t v) {
    asm volatile("st.shared.b32 [%0], %1;" :: "r"(addr), "r"(v) : "memory");
}
__device__ __forceinline__ void sts64f(uint32_t addr, float a, float b) {
    asm volatile("st.shared.v2.f32 [%0], {%1,%2};" :: "r"(addr), "f"(a), "f"(b)
                 : "memory");
}
__device__ __forceinline__ uint32_t lds32(uint32_t addr) {
    uint32_t v;
    asm volatile("ld.shared.b32 %0, [%1];" : "=r"(v) : "r"(addr));
    return v;
}
__device__ __forceinline__ float2 lds64f(uint32_t addr) {
    float2 v;
    asm volatile("ld.shared.v2.f32 {%0,%1}, [%2];"
                 : "=f"(v.x), "=f"(v.y) : "r"(addr));
    return v;
}
__device__ __forceinline__ float4 lds128f(uint32_t addr) {
    float4 v;
    asm volatile("ld.shared.v4.f32 {%0,%1,%2,%3}, [%4];"
                 : "=f"(v.x), "=f"(v.y), "=f"(v.z), "=f"(v.w) : "r"(addr));
    return v;
}
__device__ __forceinline__ uint32_t pack2h(float a, float b) {
    __half2 h2 = __floats2half2_rn(a, b);
    return *(uint32_t*)&h2;
}

__device__ __forceinline__ float sigm(float x) {
    return __fdividef(1.0f, 1.0f + __expf(-x));
}
__device__ __forceinline__ float tanh_(float x) {
    return __fmaf_rn(2.0f, sigm(2.0f * x), -1.0f);
}

// stage Whh (192x64 fp32) as a single fp16 SW128-swizzled tile
__device__ __forceinline__ void stage_whh(char* smem, const float* Wc, int tid) {
    for (int idx = tid; idx < GG * HH; idx += BT) {
        int g = idx >> 6, k = idx & 63;
        uint32_t off = (uint32_t)g * 128u + (uint32_t)k * 2u;
        uint32_t sw = off ^ ((off >> 3) & 0x70);
        *(__half*)(smem + W_T + sw) = __float2half_rn(Wc[idx]);
    }
}

// load B tiles for chunk ch and issue its 24 HMMA into acc
__device__ __forceinline__ void issue_chunk(uint32_t sb, uint32_t bRow,
                                            uint32_t bk0, uint32_t bk1,
                                            const uint32_t (&Ah)[2][4][4],
                                            float (*acc)[2][4], int ch) {
    #pragma unroll
    for (int g = 0; g < 3; g++)
        #pragma unroll
        for (int mt = 0; mt < 2; mt++)
            #pragma unroll
            for (int q = 0; q < 4; q++) acc[g][mt][q] = 0.0f;

    uint32_t B0[3][8];
    #pragma unroll
    for (int g = 0; g < 3; g++) {
        uint32_t wb = sb + W_T + (uint32_t)(g*64 + ch*8) * 128u + bRow;
        ldsm4(&B0[g][0], wb + bk0);
        ldsm4(&B0[g][4], wb + bk1);
    }
    #pragma unroll
    for (int g = 0; g < 3; g++)
        #pragma unroll
        for (int mt = 0; mt < 2; mt++)
            #pragma unroll
            for (int kt = 0; kt < 4; kt++) {
                int bi = (kt >> 1) * 4 + (kt & 1) * 2;
                hmma(acc[g][mt], Ah[mt][kt], B0[g][bi], B0[g][bi + 1]);
            }
}

extern "C" __global__ void __launch_bounds__(BT, 3)
rnn_kernel(const float* __restrict__ X,
           const float* __restrict__ eWih, const float* __restrict__ eWhh,
           const float* __restrict__ ebih, const float* __restrict__ ebhh,
           const float* __restrict__ dWih, const float* __restrict__ dWhh,
           const float* __restrict__ dbih, const float* __restrict__ dbhh,
           const float* __restrict__ linW, const float* __restrict__ linb)
{
    extern __shared__ char smem[];
    const uint32_t sb = smem_u32(smem);
    float* sCst = (float*)(smem + CST_O);
    float* sLin = (float*)(smem + LIN_O);

    const int tid  = threadIdx.x;
    const int lane = tid & 31;
    const int w    = tid >> 5;
    const int l3   = lane & 3;
    const int qr   = lane >> 2;
    const int c    = blockIdx.y;
    const int r    = blockIdx.x * BT + tid;
    const int rr   = (r < BNR) ? r : (BNR - 1);

    // ---- stage encoder weights ----
    stage_whh(smem, eWhh + (size_t)c * GG * HH, tid);
    for (int u = tid; u < HH; u += BT) {
        int base = c * GG;
        sCst[u*12+0]  = eWih[(base + u) * 2 + 0];
        sCst[u*12+1]  = eWih[(base + u) * 2 + 1];
        sCst[u*12+2]  = ebih[base + u] + ebhh[base + u];
        sCst[u*12+3]  = 0.0f;
        sCst[u*12+4]  = eWih[(base + 64 + u) * 2 + 0];
        sCst[u*12+5]  = eWih[(base + 64 + u) * 2 + 1];
        sCst[u*12+6]  = ebih[base + 64 + u] + ebhh[base + 64 + u];
        sCst[u*12+7]  = 0.0f;
        sCst[u*12+8]  = eWih[(base + 128 + u) * 2 + 0];
        sCst[u*12+9]  = eWih[(base + 128 + u) * 2 + 1];
        sCst[u*12+10] = ebih[base + 128 + u];
        sCst[u*12+11] = ebhh[base + 128 + u];
    }
    for (int i = tid; i < 4096; i += BT) ((uint32_t*)(smem + A_T))[i] = 0u;
    __syncthreads();

    // ---- per-lane address constants ----
    const int rb = lane & 15;
    const uint32_t aBase0 = sb + A_T + (uint32_t)(w*32 + rb) * 128u;
    const uint32_t aBase1 = aBase0 + 16u*128u;
    const uint32_t akh  = ((uint32_t)lane >> 4) * 16u;
    const uint32_t axor = ((uint32_t)(rb & 7)) << 4;
    uint32_t akoff[4];
    #pragma unroll
    for (int kt = 0; kt < 4; kt++) akoff[kt] = ((uint32_t)kt*32u + akh) ^ axor;

    const uint32_t bg    = lane & 7;
    const uint32_t bkoff = ((uint32_t)lane >> 3) * 16u;
    const uint32_t bxor  = bg << 4;
    const uint32_t bk0 = (0u  + bkoff) ^ bxor;
    const uint32_t bk1 = (64u + bkoff) ^ bxor;
    const uint32_t bRow = bg * 128u;

    // fragment-row constants: rows i=0..3 -> warp-local row qr + {0,8,16,24}
    uint32_t hbase[4], hsw[4], xaddr[4];
    int growG[4];
    #pragma unroll
    for (int i = 0; i < 4; i++) {
        int grow = w*32 + (i>>1)*16 + (i&1)*8 + qr;
        growG[i] = blockIdx.x * BT + grow;
        hbase[i] = sb + A_T + (uint32_t)grow * 128u;
        hsw[i]   = ((uint32_t)(grow & 7)) << 4;
        xaddr[i] = sb + X_O + (uint32_t)grow * 8u;
    }
    const uint32_t colb = (uint32_t)(l3 * 4);       // byte offset of unit pair in row
    const uint32_t cstb = sb + CST_O + (uint32_t)(l3 * 2) * 48u;  // + ch*8*48
    const uint32_t linb_a = sb + LIN_O + (uint32_t)(l3 * 2) * 4u;

    const float* xr = X + (size_t)rr * (TT * 2);
    float lb = 0.0f;

    #pragma unroll 1
    for (int t = 0; t < 2 * TT; t++) {
        if (t == TT) {   // restage decoder weights
            __syncthreads();
            stage_whh(smem, dWhh + (size_t)c * GG * HH, tid);
            for (int u = tid; u < HH; u += BT) {
                int base = c * GG;
                sCst[u*12+0]  = dWih[base + u];
                sCst[u*12+1]  = 0.0f;
                sCst[u*12+2]  = dbih[base + u] + dbhh[base + u];
                sCst[u*12+4]  = dWih[base + 64 + u];
                sCst[u*12+5]  = 0.0f;
                sCst[u*12+6]  = dbih[base + 64 + u] + dbhh[base + 64 + u];
                sCst[u*12+8]  = dWih[base + 128 + u];
                sCst[u*12+9]  = 0.0f;
                sCst[u*12+10] = dbih[base + 128 + u];
                sCst[u*12+11] = dbhh[base + 128 + u];
            }
            for (int k = tid; k < HH; k += BT) sLin[k] = linW[c*HH + k];
            __syncthreads();
            lb = linb[c];
        }

        if (t < TT) {    // stage this step's input (own row -> own warp region)
            float2 xv = *(const float2*)(xr + 2*t);
            sts64f(sb + X_O + (uint32_t)tid * 8u, xv.x, xv.y);
        }
        __syncwarp();    // prev-step hn/sX stores + x staging visible

        // load this warp's A fragments (h fp16)
        uint32_t Ah[2][4][4];
        #pragma unroll
        for (int kt = 0; kt < 4; kt++) {
            ldsm4(Ah[0][kt], aBase0 + akoff[kt]);
            ldsm4(Ah[1][kt], aBase1 + akoff[kt]);
        }

        // per-row inputs
        float x0[4], x1[4], v[4];
        #pragma unroll
        for (int i = 0; i < 4; i++) {
            float2 xv = lds64f(xaddr[i]);
            x0[i] = xv.x;
            x1[i] = (t < TT) ? xv.y : 0.0f;
            v[i] = 0.0f;
        }

        // ---- software-pipelined chunk loop ----
        float accbuf[2][3][2][4];
        issue_chunk(sb, bRow, bk0, bk1, Ah, accbuf[0], 0);

        #pragma unroll
        for (int ch = 0; ch < 8; ch++) {
            if (ch < 7)
                issue_chunk(sb, bRow, bk0, bk1, Ah, accbuf[(ch + 1) & 1], ch + 1);
            float (*acc)[2][4] = accbuf[ch & 1];

            // per-unit-pair constants (broadcast across row groups)
            uint32_t cb = cstb + (uint32_t)(ch * 8) * 48u;
            float4 cr0 = lds128f(cb);       float4 cz0 = lds128f(cb + 16);
            float4 cn0 = lds128f(cb + 32);
            float4 cr1 = lds128f(cb + 48);  float4 cz1 = lds128f(cb + 64);
            float4 cn1 = lds128f(cb + 80);
            float2 lw  = lds64f(linb_a + (uint32_t)(ch * 32));

            uint32_t choff = (uint32_t)(ch * 16) + colb;

            #pragma unroll
            for (int i = 0; i < 4; i++) {
                const int mt = i >> 1, p = i & 1;
                float gr0 = acc[0][mt][2*p],   gr1 = acc[0][mt][2*p+1];
                float gz0 = acc[1][mt][2*p],   gz1 = acc[1][mt][2*p+1];
                float gn0 = acc[2][mt][2*p],   gn1 = acc[2][mt][2*p+1];

                uint32_t haddr = hbase[i] + (choff ^ hsw[i]);
                uint32_t hraw = lds32(haddr);
                float2 ho = __half22float2(*(__half2*)&hraw);

                float rg0 = sigm(gr0 + fmaf(cr0.x, x0[i], fmaf(cr0.y, x1[i], cr0.z)));
                float zg0 = sigm(gz0 + fmaf(cz0.x, x0[i], fmaf(cz0.y, x1[i], cz0.z)));
                float gi0 = fmaf(cn0.x, x0[i], fmaf(cn0.y, x1[i], cn0.z));
                float ng0 = tanh_(fmaf(rg0, gn0 + cn0.w, gi0));
                float hn0 = fmaf(zg0, ho.x - ng0, ng0);

                float rg1 = sigm(gr1 + fmaf(cr1.x, x0[i], fmaf(cr1.y, x1[i], cr1.z)));
                float zg1 = sigm(gz1 + fmaf(cz1.x, x0[i], fmaf(cz1.y, x1[i], cz1.z)));
                float gi1 = fmaf(cn1.x, x0[i], fmaf(cn1.y, x1[i], cn1.z));
                float ng1 = tanh_(fmaf(rg1, gn1 + cn1.w, gi1));
                float hn1 = fmaf(zg1, ho.y - ng1, ng1);

                sts32(haddr, pack2h(hn0, hn1));

                if (t >= TT)
                    v[i] = fmaf(hn0, lw.x, fmaf(hn1, lw.y, v[i]));
            }
        }

        if (t >= TT) {   // decoder: reduce lin projection, write, feed back
            const int td = t - TT;
            #pragma unroll
            for (int i = 0; i < 4; i++) {
                v[i] += __shfl_xor_sync(0xFFFFFFFFu, v[i], 1);
                v[i] += __shfl_xor_sync(0xFFFFFFFFu, v[i], 2);
            }
            if (l3 == 0) {
                #pragma unroll
                for (int i = 0; i < 4; i++) {
                    float val = v[i] + lb;
                    if (growG[i] < BNR)
                        g_vals[(growG[i] * TT + td) * CC + c] = val;
                    sts64f(xaddr[i], val, 0.0f);
                }
            }
        } else if (t == TT - 1) {
            // decoder initial input = last x0: already in sX.x; x1 forced 0 on read
        }
    }
}

// out[b,n,t] = sum_c vals[b,n,t,c] * softmax(embed[n])[c]
extern "C" __global__ void mix_kernel(const float* __restrict__ embed,
                                      float* __restrict__ out)
{
    int i = blockIdx.x * blockDim.x + threadIdx.x;   // i = r*12 + t
    if (i >= BNR * TT) return;
    int n = (i / TT) % NN;
    const float* e = embed + n * CC;
    float m = e[0];
    #pragma unroll
    for (int cc = 1; cc < CC; cc++) m = fmaxf(m, e[cc]);
    const float* v = g_vals + i * CC;
    float s = 0.0f, acc = 0.0f;
    #pragma unroll
    for (int cc = 0; cc < CC; cc++) {
        float ww = __expf(e[cc] - m);
        s += ww;
        acc += v[cc] * ww;
    }
    out[i] = __fdividef(acc, s);
}

extern "C" void kernel_launch(void* const* d_in, const int* in_sizes, int n_in,
                              void* d_out, int out_size)
{
    // metadata order: A, X, enc_Wih, enc_Whh, enc_bih, enc_bhh,
    //                 dec_Wih, dec_Whh, dec_bih, dec_bhh, lin_W, lin_b, embed
    const float* X     = (const float*)d_in[1];
    const float* eWih  = (const float*)d_in[2];
    const float* eWhh  = (const float*)d_in[3];
    const float* ebih  = (const float*)d_in[4];
    const float* ebhh  = (const float*)d_in[5];
    const float* dWih  = (const float*)d_in[6];
    const float* dWhh  = (const float*)d_in[7];
    const float* dbih  = (const float*)d_in[8];
    const float* dbhh  = (const float*)d_in[9];
    const float* linW  = (const float*)d_in[10];
    const float* linb  = (const float*)d_in[11];
    const float* embed = (const float*)d_in[12];
    float* out = (float*)d_out;

    cudaFuncSetAttribute((const void*)rnn_kernel,
                         cudaFuncAttributeMaxDynamicSharedMemorySize, SMEM_BYTES);

    dim3 grid((BNR + BT - 1) / BT, CC);   // (82, 10)
    rnn_kernel<<<grid, BT, SMEM_BYTES>>>(X, eWih, eWhh, ebih, ebhh,
                                         dWih, dWhh, dbih, dbhh, linW, linb);
    mix_kernel<<<(BNR * TT + 255) / 256, 256>>>(embed, out);
}

// round 8
// speedup vs baseline: 7.4393x; 1.3399x over previous
#include <cuda_runtime.h>
#include <cuda_fp16.h>
#include <cstdint>

#define BT  128
#define HH  64
#define GG  192
#define TT  12
#define CC  10
#define NN  325
#define BB  32
#define BNR (BB*NN)

// ---- SMEM byte offsets ----
#define A_T    0u        // h fp16: 128 rows x 128B (SW128 swizzled)
#define W_T    16384u    // Whh fp16: 192 rows x 128B
#define CST_O  40960u    // 64 units x 12 floats {r: w0,w1,bsum,0 | z: w0,w1,bsum,0 | n: w0,w1,bin,bhn}
#define X_O    44032u    // 128 x float2 per-row input (x0,x1)
#define LIN_O  45056u    // 64 floats lin_W + lin_b
#define SMEM_BYTES 45568

__device__ float g_vals[BNR * TT * CC];

// ------------------------- helpers -------------------------
__device__ __forceinline__ uint32_t smem_u32(const void* p) {
    uint32_t a;
    asm("{ .reg .u64 t; cvta.to.shared.u64 t, %1; cvt.u32.u64 %0, t; }"
        : "=r"(a) : "l"(p));
    return a;
}
__device__ __forceinline__ void ldsm4(uint32_t* r, uint32_t addr) {
    asm volatile("ldmatrix.sync.aligned.m8n8.x4.shared.b16 {%0,%1,%2,%3}, [%4];"
                 : "=r"(r[0]), "=r"(r[1]), "=r"(r[2]), "=r"(r[3]) : "r"(addr));
}
__device__ __forceinline__ void hmma(float* d, const uint32_t* a,
                                     uint32_t b0, uint32_t b1) {
    asm volatile(
        "mma.sync.aligned.m16n8k16.row.col.f32.f16.f16.f32 "
        "{%0,%1,%2,%3}, {%4,%5,%6,%7}, {%8,%9}, {%0,%1,%2,%3};"
        : "+f"(d[0]), "+f"(d[1]), "+f"(d[2]), "+f"(d[3])
        : "r"(a[0]), "r"(a[1]), "r"(a[2]), "r"(a[3]), "r"(b0), "r"(b1));
}
__device__ __forceinline__ void sts32(uint32_t addr, uint32_t v) {
    asm volatile("st.shared.b32 [%0], %1;" :: "r"(addr), "r"(v) : "memory");
}
__device__ __forceinline__ void sts64f(uint32_t addr, float a, float b) {
    asm volatile("st.shared.v2.f32 [%0], {%1,%2};" :: "r"(addr), "f"(a), "f"(b)
                 : "memory");
}
__device__ __forceinline__ uint32_t lds32(uint32_t addr) {
    uint32_t v;
    asm volatile("ld.shared.b32 %0, [%1];" : "=r"(v) : "r"(addr));
    return v;
}
__device__ __forceinline__ float2 lds64f(uint32_t addr) {
    float2 v;
    asm volatile("ld.shared.v2.f32 {%0,%1}, [%2];"
                 : "=f"(v.x), "=f"(v.y) : "r"(addr));
    return v;
}
__device__ __forceinline__ float4 lds128f(uint32_t addr) {
    float4 v;
    asm volatile("ld.shared.v4.f32 {%0,%1,%2,%3}, [%4];"
                 : "=f"(v.x), "=f"(v.y), "=f"(v.z), "=f"(v.w) : "r"(addr));
    return v;
}
__device__ __forceinline__ uint32_t pack2h(float a, float b) {
    __half2 h2 = __floats2half2_rn(a, b);
    return *(uint32_t*)&h2;
}

// single-MUFU transcendentals (MUFU.TANH)
__device__ __forceinline__ float tanhx(float x) {
    float y; asm("tanh.approx.f32 %0, %1;" : "=f"(y) : "f"(x)); return y;
}
__device__ __forceinline__ float sigm(float x) {
    return fmaf(0.5f, tanhx(0.5f * x), 0.5f);
}

// stage Whh (192x64 fp32) as a single fp16 SW128-swizzled tile
__device__ __forceinline__ void stage_whh(char* smem, const float* Wc, int tid) {
    for (int idx = tid; idx < GG * HH; idx += BT) {
        int g = idx >> 6, k = idx & 63;
        uint32_t off = (uint32_t)g * 128u + (uint32_t)k * 2u;
        uint32_t sw = off ^ ((off >> 3) & 0x70);
        *(__half*)(smem + W_T + sw) = __float2half_rn(Wc[idx]);
    }
}

// load B tiles for chunk ch and issue its 24 HMMA into acc
__device__ __forceinline__ void issue_chunk(uint32_t sb, uint32_t bRow,
                                            uint32_t bk0, uint32_t bk1,
                                            const uint32_t (&Ah)[2][4][4],
                                            float (*acc)[2][4], int ch) {
    #pragma unroll
    for (int g = 0; g < 3; g++)
        #pragma unroll
        for (int mt = 0; mt < 2; mt++)
            #pragma unroll
            for (int q = 0; q < 4; q++) acc[g][mt][q] = 0.0f;

    uint32_t B0[3][8];
    #pragma unroll
    for (int g = 0; g < 3; g++) {
        uint32_t wb = sb + W_T + (uint32_t)(g*64 + ch*8) * 128u + bRow;
        ldsm4(&B0[g][0], wb + bk0);
        ldsm4(&B0[g][4], wb + bk1);
    }
    #pragma unroll
    for (int g = 0; g < 3; g++)
        #pragma unroll
        for (int mt = 0; mt < 2; mt++)
            #pragma unroll
            for (int kt = 0; kt < 4; kt++) {
                int bi = (kt >> 1) * 4 + (kt & 1) * 2;
                hmma(acc[g][mt], Ah[mt][kt], B0[g][bi], B0[g][bi + 1]);
            }
}

extern "C" __global__ void __launch_bounds__(BT, 3)
rnn_kernel(const float* __restrict__ X,
           const float* __restrict__ eWih, const float* __restrict__ eWhh,
           const float* __restrict__ ebih, const float* __restrict__ ebhh,
           const float* __restrict__ dWih, const float* __restrict__ dWhh,
           const float* __restrict__ dbih, const float* __restrict__ dbhh,
           const float* __restrict__ linW, const float* __restrict__ linb)
{
    extern __shared__ char smem[];
    const uint32_t sb = smem_u32(smem);
    float* sCst = (float*)(smem + CST_O);
    float* sLin = (float*)(smem + LIN_O);

    const int tid  = threadIdx.x;
    const int lane = tid & 31;
    const int w    = tid >> 5;
    const int l3   = lane & 3;
    const int qr   = lane >> 2;
    const int c    = blockIdx.y;
    const int r    = blockIdx.x * BT + tid;
    const int rr   = (r < BNR) ? r : (BNR - 1);

    // ---- stage encoder weights ----
    stage_whh(smem, eWhh + (size_t)c * GG * HH, tid);
    for (int u = tid; u < HH; u += BT) {
        int base = c * GG;
        sCst[u*12+0]  = eWih[(base + u) * 2 + 0];
        sCst[u*12+1]  = eWih[(base + u) * 2 + 1];
        sCst[u*12+2]  = ebih[base + u] + ebhh[base + u];
        sCst[u*12+3]  = 0.0f;
        sCst[u*12+4]  = eWih[(base + 64 + u) * 2 + 0];
        sCst[u*12+5]  = eWih[(base + 64 + u) * 2 + 1];
        sCst[u*12+6]  = ebih[base + 64 + u] + ebhh[base + 64 + u];
        sCst[u*12+7]  = 0.0f;
        sCst[u*12+8]  = eWih[(base + 128 + u) * 2 + 0];
        sCst[u*12+9]  = eWih[(base + 128 + u) * 2 + 1];
        sCst[u*12+10] = ebih[base + 128 + u];
        sCst[u*12+11] = ebhh[base + 128 + u];
    }
    for (int i = tid; i < 4096; i += BT) ((uint32_t*)(smem + A_T))[i] = 0u;
    __syncthreads();

    // ---- per-lane address constants ----
    const int rb = lane & 15;
    const uint32_t aBase0 = sb + A_T + (uint32_t)(w*32 + rb) * 128u;
    const uint32_t aBase1 = aBase0 + 16u*128u;
    const uint32_t akh  = ((uint32_t)lane >> 4) * 16u;
    const uint32_t axor = ((uint32_t)(rb & 7)) << 4;
    uint32_t akoff[4];
    #pragma unroll
    for (int kt = 0; kt < 4; kt++) akoff[kt] = ((uint32_t)kt*32u + akh) ^ axor;

    const uint32_t bg    = lane & 7;
    const uint32_t bkoff = ((uint32_t)lane >> 3) * 16u;
    const uint32_t bxor  = bg << 4;
    const uint32_t bk0 = (0u  + bkoff) ^ bxor;
    const uint32_t bk1 = (64u + bkoff) ^ bxor;
    const uint32_t bRow = bg * 128u;

    // fragment-row constants: rows i=0..3 -> warp-local row qr + {0,8,16,24}
    uint32_t hbase[4], hsw[4], xaddr[4];
    int growG[4];
    #pragma unroll
    for (int i = 0; i < 4; i++) {
        int grow = w*32 + (i>>1)*16 + (i&1)*8 + qr;
        growG[i] = blockIdx.x * BT + grow;
        hbase[i] = sb + A_T + (uint32_t)grow * 128u;
        hsw[i]   = ((uint32_t)(grow & 7)) << 4;
        xaddr[i] = sb + X_O + (uint32_t)grow * 8u;
    }
    const uint32_t colb = (uint32_t)(l3 * 4);       // byte offset of unit pair in row
    const uint32_t cstb = sb + CST_O + (uint32_t)(l3 * 2) * 48u;  // + ch*8*48
    const uint32_t linb_a = sb + LIN_O + (uint32_t)(l3 * 2) * 4u;

    const float* xr = X + (size_t)rr * (TT * 2);
    float lb = 0.0f;

    #pragma unroll 1
    for (int t = 0; t < 2 * TT; t++) {
        if (t == TT) {   // restage decoder weights
            __syncthreads();
            stage_whh(smem, dWhh + (size_t)c * GG * HH, tid);
            for (int u = tid; u < HH; u += BT) {
                int base = c * GG;
                sCst[u*12+0]  = dWih[base + u];
                sCst[u*12+1]  = 0.0f;
                sCst[u*12+2]  = dbih[base + u] + dbhh[base + u];
                sCst[u*12+4]  = dWih[base + 64 + u];
                sCst[u*12+5]  = 0.0f;
                sCst[u*12+6]  = dbih[base + 64 + u] + dbhh[base + 64 + u];
                sCst[u*12+8]  = dWih[base + 128 + u];
                sCst[u*12+9]  = 0.0f;
                sCst[u*12+10] = dbih[base + 128 + u];
                sCst[u*12+11] = dbhh[base + 128 + u];
            }
            for (int k = tid; k < HH; k += BT) sLin[k] = linW[c*HH + k];
            __syncthreads();
            lb = linb[c];
        }

        if (t < TT) {    // stage this step's input (own row -> own warp region)
            float2 xv = *(const float2*)(xr + 2*t);
            sts64f(sb + X_O + (uint32_t)tid * 8u, xv.x, xv.y);
        }
        __syncwarp();    // prev-step hn/sX stores + x staging visible

        // load this warp's A fragments (h fp16)
        uint32_t Ah[2][4][4];
        #pragma unroll
        for (int kt = 0; kt < 4; kt++) {
            ldsm4(Ah[0][kt], aBase0 + akoff[kt]);
            ldsm4(Ah[1][kt], aBase1 + akoff[kt]);
        }

        // per-row inputs
        float x0[4], x1[4], v[4];
        #pragma unroll
        for (int i = 0; i < 4; i++) {
            float2 xv = lds64f(xaddr[i]);
            x0[i] = xv.x;
            x1[i] = (t < TT) ? xv.y : 0.0f;
            v[i] = 0.0f;
        }

        // ---- software-pipelined chunk loop ----
        float accbuf[2][3][2][4];
        issue_chunk(sb, bRow, bk0, bk1, Ah, accbuf[0], 0);

        #pragma unroll
        for (int ch = 0; ch < 8; ch++) {
            if (ch < 7)
                issue_chunk(sb, bRow, bk0, bk1, Ah, accbuf[(ch + 1) & 1], ch + 1);
            float (*acc)[2][4] = accbuf[ch & 1];

            // per-unit-pair constants (broadcast across row groups)
            uint32_t cb = cstb + (uint32_t)(ch * 8) * 48u;
            float4 cr0 = lds128f(cb);       float4 cz0 = lds128f(cb + 16);
            float4 cn0 = lds128f(cb + 32);
            float4 cr1 = lds128f(cb + 48);  float4 cz1 = lds128f(cb + 64);
            float4 cn1 = lds128f(cb + 80);
            float2 lw  = lds64f(linb_a + (uint32_t)(ch * 32));

            uint32_t choff = (uint32_t)(ch * 16) + colb;

            #pragma unroll
            for (int i = 0; i < 4; i++) {
                const int mt = i >> 1, p = i & 1;
                float gr0 = acc[0][mt][2*p],   gr1 = acc[0][mt][2*p+1];
                float gz0 = acc[1][mt][2*p],   gz1 = acc[1][mt][2*p+1];
                float gn0 = acc[2][mt][2*p],   gn1 = acc[2][mt][2*p+1];

                uint32_t haddr = hbase[i] + (choff ^ hsw[i]);
                uint32_t hraw = lds32(haddr);
                float2 ho = __half22float2(*(__half2*)&hraw);

                float rg0 = sigm(gr0 + fmaf(cr0.x, x0[i], fmaf(cr0.y, x1[i], cr0.z)));
                float zg0 = sigm(gz0 + fmaf(cz0.x, x0[i], fmaf(cz0.y, x1[i], cz0.z)));
                float gi0 = fmaf(cn0.x, x0[i], fmaf(cn0.y, x1[i], cn0.z));
                float ng0 = tanhx(fmaf(rg0, gn0 + cn0.w, gi0));
                float hn0 = fmaf(zg0, ho.x - ng0, ng0);

                float rg1 = sigm(gr1 + fmaf(cr1.x, x0[i], fmaf(cr1.y, x1[i], cr1.z)));
                float zg1 = sigm(gz1 + fmaf(cz1.x, x0[i], fmaf(cz1.y, x1[i], cz1.z)));
                float gi1 = fmaf(cn1.x, x0[i], fmaf(cn1.y, x1[i], cn1.z));
                float ng1 = tanhx(fmaf(rg1, gn1 + cn1.w, gi1));
                float hn1 = fmaf(zg1, ho.y - ng1, ng1);

                sts32(haddr, pack2h(hn0, hn1));

                if (t >= TT)
                    v[i] = fmaf(hn0, lw.x, fmaf(hn1, lw.y, v[i]));
            }
        }

        if (t >= TT) {   // decoder: reduce lin projection, write, feed back
            const int td = t - TT;
            #pragma unroll
            for (int i = 0; i < 4; i++) {
                v[i] += __shfl_xor_sync(0xFFFFFFFFu, v[i], 1);
                v[i] += __shfl_xor_sync(0xFFFFFFFFu, v[i], 2);
            }
            if (l3 == 0) {
                #pragma unroll
                for (int i = 0; i < 4; i++) {
                    float val = v[i] + lb;
                    if (growG[i] < BNR)
                        g_vals[(growG[i] * TT + td) * CC + c] = val;
                    sts64f(xaddr[i], val, 0.0f);
                }
            }
        }
    }
}

// out[b,n,t] = sum_c vals[b,n,t,c] * softmax(embed[n])[c]
extern "C" __global__ void mix_kernel(const float* __restrict__ embed,
                                      float* __restrict__ out)
{
    int i = blockIdx.x * blockDim.x + threadIdx.x;   // i = r*12 + t
    if (i >= BNR * TT) return;
    int n = (i / TT) % NN;
    const float* e = embed + n * CC;
    float m = e[0];
    #pragma unroll
    for (int cc = 1; cc < CC; cc++) m = fmaxf(m, e[cc]);
    const float* v = g_vals + i * CC;
    float s = 0.0f, acc = 0.0f;
    #pragma unroll
    for (int cc = 0; cc < CC; cc++) {
        float ww = __expf(e[cc] - m);
        s += ww;
        acc += v[cc] * ww;
    }
    out[i] = __fdividef(acc, s);
}

extern "C" void kernel_launch(void* const* d_in, const int* in_sizes, int n_in,
                              void* d_out, int out_size)
{
    // metadata order: A, X, enc_Wih, enc_Whh, enc_bih, enc_bhh,
    //                 dec_Wih, dec_Whh, dec_bih, dec_bhh, lin_W, lin_b, embed
    const float* X     = (const float*)d_in[1];
    const float* eWih  = (const float*)d_in[2];
    const float* eWhh  = (const float*)d_in[3];
    const float* ebih  = (const float*)d_in[4];
    const float* ebhh  = (const float*)d_in[5];
    const float* dWih  = (const float*)d_in[6];
    const float* dWhh  = (const float*)d_in[7];
    const float* dbih  = (const float*)d_in[8];
    const float* dbhh  = (const float*)d_in[9];
    const float* linW  = (const float*)d_in[10];
    const float* linb  = (const float*)d_in[11];
    const float* embed = (const float*)d_in[12];
    float* out = (float*)d_out;

    cudaFuncSetAttribute((const void*)rnn_kernel,
                         cudaFuncAttributeMaxDynamicSharedMemorySize, SMEM_BYTES);

    dim3 grid((BNR + BT - 1) / BT, CC);   // (82, 10)
    rnn_kernel<<<grid, BT, SMEM_BYTES>>>(X, eWih, eWhh, ebih, ebhh,
                                         dWih, dWhh, dbih, dbhh, linW, linb);
    mix_kernel<<<(BNR * TT + 255) / 256, 256>>>(embed, out);
}